// round 1
// baseline (speedup 1.0000x reference)
#include <cuda_runtime.h>

// Problem constants
#define B_ 2
#define T_ 2048
#define C_ 1024
#define H_ 16
#define D_ 64
#define BT 4096          // B_*T_
#define FF 4096          // 4*C_

// ---------------- scratch (static device globals; no allocation) -----------
__device__ float g_h   [BT * C_];   // LN1 output
__device__ float g_wq  [C_ * C_];   // packed Wq [C, H*D]
__device__ float g_wk  [C_ * C_];
__device__ float g_wv  [C_ * C_];
__device__ float g_q   [BT * C_];   // [B,T,H*D]
__device__ float g_k   [BT * C_];
__device__ float g_v   [BT * C_];
__device__ float g_attn[BT * C_];   // concat heads
__device__ float g_x1  [BT * C_];   // x + attn@Wproj + bproj
__device__ float g_h2  [BT * C_];   // LN2 output
__device__ float g_f1  [BT * FF];   // relu(h2@W1+b1)

// ---------------- LayerNorm: one block per row, C=1024 --------------------
__global__ void ln_kernel(const float* __restrict__ x,
                          const float* __restrict__ sc,
                          const float* __restrict__ bi,
                          float* __restrict__ out) {
    int row = blockIdx.x;
    const float* xr = x + (size_t)row * C_;
    float* orow = out + (size_t)row * C_;
    int tid = threadIdx.x;  // 256 threads, 4 elems each

    float4 v = ((const float4*)xr)[tid];
    float s  = v.x + v.y + v.z + v.w;
    float ss = v.x*v.x + v.y*v.y + v.z*v.z + v.w*v.w;
    #pragma unroll
    for (int o = 16; o; o >>= 1) {
        s  += __shfl_xor_sync(0xffffffffu, s,  o);
        ss += __shfl_xor_sync(0xffffffffu, ss, o);
    }
    __shared__ float sm[8], sm2[8];
    if ((tid & 31) == 0) { sm[tid >> 5] = s; sm2[tid >> 5] = ss; }
    __syncthreads();
    if (tid < 32) {
        float a  = (tid < 8) ? sm[tid]  : 0.f;
        float b2 = (tid < 8) ? sm2[tid] : 0.f;
        #pragma unroll
        for (int o = 4; o; o >>= 1) {
            a  += __shfl_xor_sync(0xffffffffu, a,  o);
            b2 += __shfl_xor_sync(0xffffffffu, b2, o);
        }
        if (tid == 0) { sm[0] = a; sm2[0] = b2; }
    }
    __syncthreads();
    float mean = sm[0] * (1.f / C_);
    float var  = sm2[0] * (1.f / C_) - mean * mean;
    float rstd = rsqrtf(var + 1e-6f);

    float4 sv = ((const float4*)sc)[tid];
    float4 bv = ((const float4*)bi)[tid];
    float4 o4;
    o4.x = (v.x - mean) * rstd * sv.x + bv.x;
    o4.y = (v.y - mean) * rstd * sv.y + bv.y;
    o4.z = (v.z - mean) * rstd * sv.z + bv.z;
    o4.w = (v.w - mean) * rstd * sv.w + bv.w;
    ((float4*)orow)[tid] = o4;
}

// ---------------- pack W[H,C,D] -> Wp[C, H*D] ------------------------------
__global__ void pack_w(const float* __restrict__ W, float* __restrict__ Wp) {
    int idx = blockIdx.x * 256 + threadIdx.x;   // over C_*C_ = 1M
    int c = idx >> 10, n = idx & 1023;
    int h = n >> 6, d = n & 63;
    Wp[idx] = W[((size_t)h * C_ + c) * D_ + d];
}

// ---------------- SGEMM: C = A[M,K] @ B[K,N] (+bias)(+resid)(relu) ---------
// 128x128 tile, BK=16, 256 threads, 8x8 per-thread tile. Dims divisible.
template <int RELU>
__global__ void __launch_bounds__(256, 2) sgemm_kernel(
    const float* __restrict__ A, const float* __restrict__ Bm,
    const float* __restrict__ bias, const float* __restrict__ resid,
    float* __restrict__ C, int M, int N, int K)
{
    __shared__ float As[16][128];   // A transposed: As[k][m]
    __shared__ float Bs[16][128];   // Bs[k][n]
    int tid = threadIdx.x;
    int bm = blockIdx.y, bn = blockIdx.x;
    const float* Ab = A + (size_t)bm * 128 * K;
    const float* Bb = Bm + bn * 128;

    float acc[8][8];
    #pragma unroll
    for (int i = 0; i < 8; i++)
        #pragma unroll
        for (int j = 0; j < 8; j++) acc[i][j] = 0.f;

    int ty = tid >> 4, tx = tid & 15;

    for (int kt = 0; kt < K; kt += 16) {
        #pragma unroll
        for (int i = 0; i < 2; i++) {
            int lin = tid + i * 256;
            int r = lin >> 2, c4 = (lin & 3) << 2;
            float4 a = *(const float4*)(Ab + (size_t)r * K + kt + c4);
            As[c4 + 0][r] = a.x; As[c4 + 1][r] = a.y;
            As[c4 + 2][r] = a.z; As[c4 + 3][r] = a.w;
            int rb = lin >> 5, cb4 = (lin & 31) << 2;
            float4 b4 = *(const float4*)(Bb + (size_t)(kt + rb) * N + cb4);
            *(float4*)&Bs[rb][cb4] = b4;
        }
        __syncthreads();
        #pragma unroll
        for (int kk = 0; kk < 16; kk++) {
            float ra[8], rb[8];
            *(float4*)&ra[0] = *(float4*)&As[kk][ty * 8];
            *(float4*)&ra[4] = *(float4*)&As[kk][ty * 8 + 4];
            *(float4*)&rb[0] = *(float4*)&Bs[kk][tx * 8];
            *(float4*)&rb[4] = *(float4*)&Bs[kk][tx * 8 + 4];
            #pragma unroll
            for (int i = 0; i < 8; i++)
                #pragma unroll
                for (int j = 0; j < 8; j++)
                    acc[i][j] += ra[i] * rb[j];
        }
        __syncthreads();
    }

    int n0 = bn * 128 + tx * 8;
    #pragma unroll
    for (int i = 0; i < 8; i++) {
        int m = bm * 128 + ty * 8 + i;
        float* Crow = C + (size_t)m * N + n0;
        const float* Rrow = resid ? resid + (size_t)m * N + n0 : nullptr;
        float o[8];
        #pragma unroll
        for (int j = 0; j < 8; j++) {
            float v = acc[i][j];
            if (bias)  v += bias[n0 + j];
            if (resid) v += Rrow[j];
            if (RELU)  v = fmaxf(v, 0.f);
            o[j] = v;
        }
        *(float4*)&Crow[0] = *(float4*)&o[0];
        *(float4*)&Crow[4] = *(float4*)&o[4];
    }
}

// ---------------- flash-style causal attention -----------------------------
// Q,K,V layout [B,T,H*D]; block = 128 query rows of one (b,h); BN=64 keys.
// 256 threads: ty=tid>>3 (32, 4 rows each), tx=tid&7 (8, 8 cols each).
#define ATT_SMEM_FLOATS (64*128 + 64*64 + 64*64 + 128*68)
__global__ void __launch_bounds__(256, 2) attn_kernel(
    const float* __restrict__ Q, const float* __restrict__ K,
    const float* __restrict__ V, float* __restrict__ O)
{
    extern __shared__ float smem[];
    float* Qt = smem;                 // [64][128]  (d-major, transposed)
    float* Kt = Qt + 64 * 128;        // [64][64]   (d-major, transposed)
    float* Vs = Kt + 64 * 64;         // [64][64]   (s-major)
    float* Ps = Vs + 64 * 64;         // [128][68]
    const int PLD = 68;

    int tid = threadIdx.x;
    int b = blockIdx.y >> 4, h = blockIdx.y & 15;
    int q0 = blockIdx.x * 128;
    const float* Qb = Q + (size_t)b * T_ * C_ + h * 64;
    const float* Kb = K + (size_t)b * T_ * C_ + h * 64;
    const float* Vb = V + (size_t)b * T_ * C_ + h * 64;

    // load Q tile (transposed into Qt[d][m])
    for (int i = tid; i < 128 * 16; i += 256) {
        int m = i >> 4, d4 = (i & 15) << 2;
        float4 qv = *(const float4*)(Qb + (size_t)(q0 + m) * C_ + d4);
        Qt[(d4 + 0) * 128 + m] = qv.x; Qt[(d4 + 1) * 128 + m] = qv.y;
        Qt[(d4 + 2) * 128 + m] = qv.z; Qt[(d4 + 3) * 128 + m] = qv.w;
    }

    int ty = tid >> 3, tx = tid & 7;
    int mr = ty * 4;
    float mi[4], li[4], Oa[4][8];
    #pragma unroll
    for (int i = 0; i < 4; i++) {
        mi[i] = -1e30f; li[i] = 0.f;
        #pragma unroll
        for (int j = 0; j < 8; j++) Oa[i][j] = 0.f;
    }

    int ntiles = (q0 >> 6) + 2;
    for (int kt = 0; kt < ntiles; kt++) {
        int k0 = kt << 6;
        __syncthreads();   // prior iter's Ps/Vs reads done
        for (int i = tid; i < 64 * 16; i += 256) {
            int r = i >> 4, d4 = (i & 15) << 2;
            float4 kv = *(const float4*)(Kb + (size_t)(k0 + r) * C_ + d4);
            Kt[(d4 + 0) * 64 + r] = kv.x; Kt[(d4 + 1) * 64 + r] = kv.y;
            Kt[(d4 + 2) * 64 + r] = kv.z; Kt[(d4 + 3) * 64 + r] = kv.w;
            float4 vv = *(const float4*)(Vb + (size_t)(k0 + r) * C_ + d4);
            *(float4*)&Vs[r * 64 + d4] = vv;
        }
        __syncthreads();

        // S = Q K^T
        float S[4][8];
        #pragma unroll
        for (int i = 0; i < 4; i++)
            #pragma unroll
            for (int j = 0; j < 8; j++) S[i][j] = 0.f;
        #pragma unroll 4
        for (int d = 0; d < 64; d++) {
            float4 q4 = *(float4*)&Qt[d * 128 + mr];
            float4 ka = *(float4*)&Kt[d * 64 + tx * 8];
            float4 kb = *(float4*)&Kt[d * 64 + tx * 8 + 4];
            float qa[4] = {q4.x, q4.y, q4.z, q4.w};
            float kv[8] = {ka.x, ka.y, ka.z, ka.w, kb.x, kb.y, kb.z, kb.w};
            #pragma unroll
            for (int i = 0; i < 4; i++)
                #pragma unroll
                for (int j = 0; j < 8; j++)
                    S[i][j] += qa[i] * kv[j];
        }

        // scale (C^-0.5 = 1/32) + causal mask
        #pragma unroll
        for (int i = 0; i < 4; i++) {
            int mg = q0 + mr + i;
            #pragma unroll
            for (int j = 0; j < 8; j++) {
                int ng = k0 + tx * 8 + j;
                S[i][j] = (ng <= mg) ? S[i][j] * 0.03125f : -1e30f;
            }
        }

        // online softmax update
        #pragma unroll
        for (int i = 0; i < 4; i++) {
            float rmax = S[i][0];
            #pragma unroll
            for (int j = 1; j < 8; j++) rmax = fmaxf(rmax, S[i][j]);
            rmax = fmaxf(rmax, __shfl_xor_sync(0xffffffffu, rmax, 1));
            rmax = fmaxf(rmax, __shfl_xor_sync(0xffffffffu, rmax, 2));
            rmax = fmaxf(rmax, __shfl_xor_sync(0xffffffffu, rmax, 4));
            float mnew = fmaxf(mi[i], rmax);
            float corr = __expf(mi[i] - mnew);
            float rsum = 0.f;
            #pragma unroll
            for (int j = 0; j < 8; j++) {
                float p = __expf(S[i][j] - mnew);
                S[i][j] = p;
                rsum += p;
            }
            rsum += __shfl_xor_sync(0xffffffffu, rsum, 1);
            rsum += __shfl_xor_sync(0xffffffffu, rsum, 2);
            rsum += __shfl_xor_sync(0xffffffffu, rsum, 4);
            li[i] = li[i] * corr + rsum;
            mi[i] = mnew;
            #pragma unroll
            for (int j = 0; j < 8; j++) Oa[i][j] *= corr;
        }

        // write P to smem
        #pragma unroll
        for (int i = 0; i < 4; i++) {
            *(float4*)&Ps[(mr + i) * PLD + tx * 8]     = *(float4*)&S[i][0];
            *(float4*)&Ps[(mr + i) * PLD + tx * 8 + 4] = *(float4*)&S[i][4];
        }
        __syncthreads();

        // O += P @ V
        #pragma unroll 4
        for (int s = 0; s < 64; s++) {
            float p0 = Ps[(mr + 0) * PLD + s];
            float p1 = Ps[(mr + 1) * PLD + s];
            float p2 = Ps[(mr + 2) * PLD + s];
            float p3 = Ps[(mr + 3) * PLD + s];
            float4 va = *(float4*)&Vs[s * 64 + tx * 8];
            float4 vb = *(float4*)&Vs[s * 64 + tx * 8 + 4];
            float vv[8] = {va.x, va.y, va.z, va.w, vb.x, vb.y, vb.z, vb.w};
            #pragma unroll
            for (int j = 0; j < 8; j++) {
                Oa[0][j] += p0 * vv[j];
                Oa[1][j] += p1 * vv[j];
                Oa[2][j] += p2 * vv[j];
                Oa[3][j] += p3 * vv[j];
            }
        }
    }

    // write output (concat heads layout)
    #pragma unroll
    for (int i = 0; i < 4; i++) {
        float inv = 1.f / li[i];
        float* Orow = O + ((size_t)b * T_ + q0 + mr + i) * C_ + h * 64 + tx * 8;
        float o[8];
        #pragma unroll
        for (int j = 0; j < 8; j++) o[j] = Oa[i][j] * inv;
        *(float4*)&Orow[0] = *(float4*)&o[0];
        *(float4*)&Orow[4] = *(float4*)&o[4];
    }
}

// ---------------- launcher -------------------------------------------------
extern "C" void kernel_launch(void* const* d_in, const int* in_sizes, int n_in,
                              void* d_out, int out_size) {
    const float* x     = (const float*)d_in[0];
    const float* Wq    = (const float*)d_in[1];
    const float* Wk    = (const float*)d_in[2];
    const float* Wv    = (const float*)d_in[3];
    const float* Wproj = (const float*)d_in[4];
    const float* bproj = (const float*)d_in[5];
    const float* W1    = (const float*)d_in[6];
    const float* b1    = (const float*)d_in[7];
    const float* W2    = (const float*)d_in[8];
    const float* b2    = (const float*)d_in[9];
    const float* ln1s  = (const float*)d_in[10];
    const float* ln1b  = (const float*)d_in[11];
    const float* ln2s  = (const float*)d_in[12];
    const float* ln2b  = (const float*)d_in[13];
    float* out = (float*)d_out;

    float *h, *wq, *wk, *wv, *q, *k, *v, *attn, *x1, *h2, *f1;
    cudaGetSymbolAddress((void**)&h,    g_h);
    cudaGetSymbolAddress((void**)&wq,   g_wq);
    cudaGetSymbolAddress((void**)&wk,   g_wk);
    cudaGetSymbolAddress((void**)&wv,   g_wv);
    cudaGetSymbolAddress((void**)&q,    g_q);
    cudaGetSymbolAddress((void**)&k,    g_k);
    cudaGetSymbolAddress((void**)&v,    g_v);
    cudaGetSymbolAddress((void**)&attn, g_attn);
    cudaGetSymbolAddress((void**)&x1,   g_x1);
    cudaGetSymbolAddress((void**)&h2,   g_h2);
    cudaGetSymbolAddress((void**)&f1,   g_f1);

    const int ATT_SMEM = ATT_SMEM_FLOATS * (int)sizeof(float);  // ~100 KB
    cudaFuncSetAttribute(attn_kernel,
                         cudaFuncAttributeMaxDynamicSharedMemorySize, ATT_SMEM);

    // LN1
    ln_kernel<<<BT, 256>>>(x, ln1s, ln1b, h);
    // pack per-head weights to [C, H*D]
    pack_w<<<C_ * C_ / 256, 256>>>(Wq, wq);
    pack_w<<<C_ * C_ / 256, 256>>>(Wk, wk);
    pack_w<<<C_ * C_ / 256, 256>>>(Wv, wv);
    // QKV projections
    dim3 g1(C_ / 128, BT / 128);
    sgemm_kernel<0><<<g1, 256>>>(h, wq, nullptr, nullptr, q, BT, C_, C_);
    sgemm_kernel<0><<<g1, 256>>>(h, wk, nullptr, nullptr, k, BT, C_, C_);
    sgemm_kernel<0><<<g1, 256>>>(h, wv, nullptr, nullptr, v, BT, C_, C_);
    // attention
    attn_kernel<<<dim3(T_ / 128, B_ * H_), 256, ATT_SMEM>>>(q, k, v, attn);
    // out proj + residual
    sgemm_kernel<0><<<g1, 256>>>(attn, Wproj, bproj, x, x1, BT, C_, C_);
    // LN2
    ln_kernel<<<BT, 256>>>(x1, ln2s, ln2b, h2);
    // MLP
    sgemm_kernel<1><<<dim3(FF / 128, BT / 128), 256>>>(h2, W1, b1, nullptr, f1, BT, FF, C_);
    sgemm_kernel<0><<<g1, 256>>>(f1, W2, b2, x1, out, BT, C_, FF);
}

// round 4
// speedup vs baseline: 1.7407x; 1.7407x over previous
#include <cuda_runtime.h>
#include <cstdint>

// Problem constants
#define B_ 2
#define T_ 2048
#define C_ 1024
#define H_ 16
#define D_ 64
#define BT 4096          // B_*T_
#define FF 4096          // 4*C_

// ---------------- scratch (static device globals; no allocation) -----------
__device__ float g_h   [BT * C_];   // LN1 output
__device__ float g_wq  [C_ * C_];   // Wq^T packed: [N=H*D, K=C]
__device__ float g_wk  [C_ * C_];
__device__ float g_wv  [C_ * C_];
__device__ float g_wpt [C_ * C_];   // Wproj^T [N=C, K=C]
__device__ float g_w1t [C_ * FF];   // W1^T [N=FF, K=C]
__device__ float g_w2t [C_ * FF];   // W2^T [N=C, K=FF]
__device__ float g_q   [BT * C_];   // [B,T,H*D]
__device__ float g_k   [BT * C_];
__device__ float g_v   [BT * C_];
__device__ float g_attn[BT * C_];   // concat heads
__device__ float g_x1  [BT * C_];   // x + attn@Wproj + bproj
__device__ float g_h2  [BT * C_];   // LN2 output
__device__ float g_f1  [BT * FF];   // relu(h2@W1+b1)

// tf32 destination is a .b32 register in PTX -> "=r" constraint
__device__ __forceinline__ float to_tf32(float x) {
    uint32_t r;
    asm("cvt.rna.tf32.f32 %0, %1;" : "=r"(r) : "f"(x));
    return __uint_as_float(r);
}

// m16n8k8 tf32 mma (sm_80+ ISA; valid on sm_100)
__device__ __forceinline__ void mma8(float* c, const uint32_t* a, const uint32_t* b) {
    asm volatile(
        "mma.sync.aligned.m16n8k8.row.col.f32.tf32.tf32.f32 "
        "{%0,%1,%2,%3}, {%4,%5,%6,%7}, {%8,%9}, {%0,%1,%2,%3};"
        : "+f"(c[0]), "+f"(c[1]), "+f"(c[2]), "+f"(c[3])
        : "r"(a[0]), "r"(a[1]), "r"(a[2]), "r"(a[3]), "r"(b[0]), "r"(b[1]));
}

// ---------------- LayerNorm: one block per row, C=1024 --------------------
__global__ void ln_kernel(const float* __restrict__ x,
                          const float* __restrict__ sc,
                          const float* __restrict__ bi,
                          float* __restrict__ out) {
    int row = blockIdx.x;
    const float* xr = x + (size_t)row * C_;
    float* orow = out + (size_t)row * C_;
    int tid = threadIdx.x;

    float4 v = ((const float4*)xr)[tid];
    float s  = v.x + v.y + v.z + v.w;
    float ss = v.x*v.x + v.y*v.y + v.z*v.z + v.w*v.w;
    #pragma unroll
    for (int o = 16; o; o >>= 1) {
        s  += __shfl_xor_sync(0xffffffffu, s,  o);
        ss += __shfl_xor_sync(0xffffffffu, ss, o);
    }
    __shared__ float sm[8], sm2[8];
    if ((tid & 31) == 0) { sm[tid >> 5] = s; sm2[tid >> 5] = ss; }
    __syncthreads();
    if (tid < 32) {
        float a  = (tid < 8) ? sm[tid]  : 0.f;
        float b2 = (tid < 8) ? sm2[tid] : 0.f;
        #pragma unroll
        for (int o = 4; o; o >>= 1) {
            a  += __shfl_xor_sync(0xffffffffu, a,  o);
            b2 += __shfl_xor_sync(0xffffffffu, b2, o);
        }
        if (tid == 0) { sm[0] = a; sm2[0] = b2; }
    }
    __syncthreads();
    float mean = sm[0] * (1.f / C_);
    float var  = sm2[0] * (1.f / C_) - mean * mean;
    float rstd = rsqrtf(var + 1e-6f);

    float4 sv = ((const float4*)sc)[tid];
    float4 bv = ((const float4*)bi)[tid];
    float4 o4;
    o4.x = (v.x - mean) * rstd * sv.x + bv.x;
    o4.y = (v.y - mean) * rstd * sv.y + bv.y;
    o4.z = (v.z - mean) * rstd * sv.z + bv.z;
    o4.w = (v.w - mean) * rstd * sv.w + bv.w;
    ((float4*)orow)[tid] = o4;
}

// ---------------- tiled transpose with batch (z) ---------------------------
// dst[c*R + r] = src[r*Cc + c]; block (32,8); grid (Cc/32, R/32, Z)
__global__ void transpose_k(const float* __restrict__ src, float* __restrict__ dst,
                            int R, int Cc, long sstride, long dstride) {
    __shared__ float t[32][33];
    src += (long)blockIdx.z * sstride;
    dst += (long)blockIdx.z * dstride;
    int r0 = blockIdx.y * 32, c0 = blockIdx.x * 32;
    int x = threadIdx.x, y = threadIdx.y;
    #pragma unroll
    for (int i = 0; i < 32; i += 8)
        t[y + i][x] = src[(size_t)(r0 + y + i) * Cc + c0 + x];
    __syncthreads();
    #pragma unroll
    for (int i = 0; i < 32; i += 8)
        dst[(size_t)(c0 + y + i) * R + r0 + x] = t[x][y + i];
}

// ---------------- tf32 mma.sync GEMM ---------------------------------------
// C[M,N] = A[M,K] @ Bt[N,K]^T  (+bias)(+resid)(relu)
// CTA tile 128x128, BK=16, 256 threads (8 warps, warp tile 64x32),
// double-buffered SMEM, stride 20 (conflict-free fragment loads).
#define SA 20

template <int RELU>
__global__ void __launch_bounds__(256, 2) mma_gemm(
    const float* __restrict__ A, const float* __restrict__ Bt,
    const float* __restrict__ bias, const float* __restrict__ resid,
    float* __restrict__ Cc, int M, int N, int K)
{
    __shared__ float As[2][128 * SA];
    __shared__ float Bs[2][128 * SA];

    int tid  = threadIdx.x;
    int wid  = tid >> 5, lane = tid & 31;
    int g    = lane >> 2, r = lane & 3;
    int bm   = blockIdx.y, bn = blockIdx.x;
    int wm   = (wid & 1) * 64;       // warp m offset within CTA tile
    int wn   = (wid >> 1) * 32;      // warp n offset

    const float* Ab = A  + (size_t)bm * 128 * K;
    const float* Bb = Bt + (size_t)bn * 128 * K;

    float c[4][4][4];
    #pragma unroll
    for (int mt = 0; mt < 4; mt++)
        #pragma unroll
        for (int nt = 0; nt < 4; nt++)
            #pragma unroll
            for (int i = 0; i < 4; i++) c[mt][nt][i] = 0.f;

    // gmem staging regs (2 float4 per matrix)
    float4 ra[2], rb[2];
    int row_[2], q_[2];
    #pragma unroll
    for (int i = 0; i < 2; i++) {
        int idx = tid + i * 256;
        row_[i] = idx >> 2;
        q_[i]   = (idx & 3) << 2;
    }

    // preload chunk 0
    #pragma unroll
    for (int i = 0; i < 2; i++) {
        ra[i] = *(const float4*)(Ab + (size_t)row_[i] * K + q_[i]);
        rb[i] = *(const float4*)(Bb + (size_t)row_[i] * K + q_[i]);
    }
    #pragma unroll
    for (int i = 0; i < 2; i++) {
        float4 a = ra[i], b = rb[i];
        a.x = to_tf32(a.x); a.y = to_tf32(a.y); a.z = to_tf32(a.z); a.w = to_tf32(a.w);
        b.x = to_tf32(b.x); b.y = to_tf32(b.y); b.z = to_tf32(b.z); b.w = to_tf32(b.w);
        *(float4*)&As[0][row_[i] * SA + q_[i]] = a;
        *(float4*)&Bs[0][row_[i] * SA + q_[i]] = b;
    }
    __syncthreads();

    int nch = K >> 4;
    for (int ch = 0; ch < nch; ch++) {
        int p = ch & 1;
        // prefetch next tile from gmem
        if (ch + 1 < nch) {
            int kt = (ch + 1) << 4;
            #pragma unroll
            for (int i = 0; i < 2; i++) {
                ra[i] = *(const float4*)(Ab + (size_t)row_[i] * K + kt + q_[i]);
                rb[i] = *(const float4*)(Bb + (size_t)row_[i] * K + kt + q_[i]);
            }
        }

        // compute on buffer p
        const float* Ap = As[p];
        const float* Bp = Bs[p];
        #pragma unroll
        for (int ks = 0; ks < 2; ks++) {
            int kk = ks * 8;
            uint32_t af[4][4], bf[4][2];
            #pragma unroll
            for (int mt = 0; mt < 4; mt++) {
                int m = wm + mt * 16 + g;
                af[mt][0] = __float_as_uint(Ap[(m    ) * SA + kk + r    ]);
                af[mt][1] = __float_as_uint(Ap[(m + 8) * SA + kk + r    ]);
                af[mt][2] = __float_as_uint(Ap[(m    ) * SA + kk + r + 4]);
                af[mt][3] = __float_as_uint(Ap[(m + 8) * SA + kk + r + 4]);
            }
            #pragma unroll
            for (int nt = 0; nt < 4; nt++) {
                int n = wn + nt * 8 + g;
                bf[nt][0] = __float_as_uint(Bp[n * SA + kk + r    ]);
                bf[nt][1] = __float_as_uint(Bp[n * SA + kk + r + 4]);
            }
            #pragma unroll
            for (int mt = 0; mt < 4; mt++)
                #pragma unroll
                for (int nt = 0; nt < 4; nt++)
                    mma8(c[mt][nt], af[mt], bf[nt]);
        }

        // store prefetched tile into other buffer
        if (ch + 1 < nch) {
            int pn = p ^ 1;
            #pragma unroll
            for (int i = 0; i < 2; i++) {
                float4 a = ra[i], b = rb[i];
                a.x = to_tf32(a.x); a.y = to_tf32(a.y); a.z = to_tf32(a.z); a.w = to_tf32(a.w);
                b.x = to_tf32(b.x); b.y = to_tf32(b.y); b.z = to_tf32(b.z); b.w = to_tf32(b.w);
                *(float4*)&As[pn][row_[i] * SA + q_[i]] = a;
                *(float4*)&Bs[pn][row_[i] * SA + q_[i]] = b;
            }
        }
        __syncthreads();
    }

    // epilogue: frag (mt,nt): rows g/g+8, cols 2r/2r+1
    #pragma unroll
    for (int mt = 0; mt < 4; mt++) {
        #pragma unroll
        for (int rr = 0; rr < 2; rr++) {
            int m = bm * 128 + wm + mt * 16 + g + rr * 8;
            float* Crow = Cc + (size_t)m * N + bn * 128;
            const float* Rrow = resid ? resid + (size_t)m * N + bn * 128 : nullptr;
            #pragma unroll
            for (int nt = 0; nt < 4; nt++) {
                int nc = wn + nt * 8 + 2 * r;
                float v0 = c[mt][nt][rr * 2 + 0];
                float v1 = c[mt][nt][rr * 2 + 1];
                if (bias)  { v0 += bias[bn * 128 + nc]; v1 += bias[bn * 128 + nc + 1]; }
                if (resid) { v0 += Rrow[nc]; v1 += Rrow[nc + 1]; }
                if (RELU)  { v0 = fmaxf(v0, 0.f); v1 = fmaxf(v1, 0.f); }
                float2 o2 = make_float2(v0, v1);
                *(float2*)&Crow[nc] = o2;
            }
        }
    }
}

// ---------------- flash-style causal attention (fp32, validated) -----------
#define ATT_SMEM_FLOATS (64*128 + 64*64 + 64*64 + 128*68)
__global__ void __launch_bounds__(256, 2) attn_kernel(
    const float* __restrict__ Q, const float* __restrict__ K,
    const float* __restrict__ V, float* __restrict__ O)
{
    extern __shared__ float smemf[];
    float* Qt = smemf;
    float* Kt = Qt + 64 * 128;
    float* Vs = Kt + 64 * 64;
    float* Ps = Vs + 64 * 64;
    const int PLD = 68;

    int tid = threadIdx.x;
    int b = blockIdx.y >> 4, h = blockIdx.y & 15;
    int q0 = blockIdx.x * 128;
    const float* Qb = Q + (size_t)b * T_ * C_ + h * 64;
    const float* Kb = K + (size_t)b * T_ * C_ + h * 64;
    const float* Vb = V + (size_t)b * T_ * C_ + h * 64;

    for (int i = tid; i < 128 * 16; i += 256) {
        int m = i >> 4, d4 = (i & 15) << 2;
        float4 qv = *(const float4*)(Qb + (size_t)(q0 + m) * C_ + d4);
        Qt[(d4 + 0) * 128 + m] = qv.x; Qt[(d4 + 1) * 128 + m] = qv.y;
        Qt[(d4 + 2) * 128 + m] = qv.z; Qt[(d4 + 3) * 128 + m] = qv.w;
    }

    int ty = tid >> 3, tx = tid & 7;
    int mr = ty * 4;
    float mi[4], li[4], Oa[4][8];
    #pragma unroll
    for (int i = 0; i < 4; i++) {
        mi[i] = -1e30f; li[i] = 0.f;
        #pragma unroll
        for (int j = 0; j < 8; j++) Oa[i][j] = 0.f;
    }

    int ntiles = (q0 >> 6) + 2;
    for (int kt = 0; kt < ntiles; kt++) {
        int k0 = kt << 6;
        __syncthreads();
        for (int i = tid; i < 64 * 16; i += 256) {
            int rr = i >> 4, d4 = (i & 15) << 2;
            float4 kv = *(const float4*)(Kb + (size_t)(k0 + rr) * C_ + d4);
            Kt[(d4 + 0) * 64 + rr] = kv.x; Kt[(d4 + 1) * 64 + rr] = kv.y;
            Kt[(d4 + 2) * 64 + rr] = kv.z; Kt[(d4 + 3) * 64 + rr] = kv.w;
            float4 vv = *(const float4*)(Vb + (size_t)(k0 + rr) * C_ + d4);
            *(float4*)&Vs[rr * 64 + d4] = vv;
        }
        __syncthreads();

        float S[4][8];
        #pragma unroll
        for (int i = 0; i < 4; i++)
            #pragma unroll
            for (int j = 0; j < 8; j++) S[i][j] = 0.f;
        #pragma unroll 4
        for (int d = 0; d < 64; d++) {
            float4 q4 = *(float4*)&Qt[d * 128 + mr];
            float4 ka = *(float4*)&Kt[d * 64 + tx * 8];
            float4 kb = *(float4*)&Kt[d * 64 + tx * 8 + 4];
            float qa[4] = {q4.x, q4.y, q4.z, q4.w};
            float kv[8] = {ka.x, ka.y, ka.z, ka.w, kb.x, kb.y, kb.z, kb.w};
            #pragma unroll
            for (int i = 0; i < 4; i++)
                #pragma unroll
                for (int j = 0; j < 8; j++)
                    S[i][j] += qa[i] * kv[j];
        }

        #pragma unroll
        for (int i = 0; i < 4; i++) {
            int mg = q0 + mr + i;
            #pragma unroll
            for (int j = 0; j < 8; j++) {
                int ng = k0 + tx * 8 + j;
                S[i][j] = (ng <= mg) ? S[i][j] * 0.03125f : -1e30f;
            }
        }

        #pragma unroll
        for (int i = 0; i < 4; i++) {
            float rmax = S[i][0];
            #pragma unroll
            for (int j = 1; j < 8; j++) rmax = fmaxf(rmax, S[i][j]);
            rmax = fmaxf(rmax, __shfl_xor_sync(0xffffffffu, rmax, 1));
            rmax = fmaxf(rmax, __shfl_xor_sync(0xffffffffu, rmax, 2));
            rmax = fmaxf(rmax, __shfl_xor_sync(0xffffffffu, rmax, 4));
            float mnew = fmaxf(mi[i], rmax);
            float corr = __expf(mi[i] - mnew);
            float rsum = 0.f;
            #pragma unroll
            for (int j = 0; j < 8; j++) {
                float p = __expf(S[i][j] - mnew);
                S[i][j] = p;
                rsum += p;
            }
            rsum += __shfl_xor_sync(0xffffffffu, rsum, 1);
            rsum += __shfl_xor_sync(0xffffffffu, rsum, 2);
            rsum += __shfl_xor_sync(0xffffffffu, rsum, 4);
            li[i] = li[i] * corr + rsum;
            mi[i] = mnew;
            #pragma unroll
            for (int j = 0; j < 8; j++) Oa[i][j] *= corr;
        }

        #pragma unroll
        for (int i = 0; i < 4; i++) {
            *(float4*)&Ps[(mr + i) * PLD + tx * 8]     = *(float4*)&S[i][0];
            *(float4*)&Ps[(mr + i) * PLD + tx * 8 + 4] = *(float4*)&S[i][4];
        }
        __syncthreads();

        #pragma unroll 4
        for (int s = 0; s < 64; s++) {
            float p0 = Ps[(mr + 0) * PLD + s];
            float p1 = Ps[(mr + 1) * PLD + s];
            float p2 = Ps[(mr + 2) * PLD + s];
            float p3 = Ps[(mr + 3) * PLD + s];
            float4 va = *(float4*)&Vs[s * 64 + tx * 8];
            float4 vb = *(float4*)&Vs[s * 64 + tx * 8 + 4];
            float vv[8] = {va.x, va.y, va.z, va.w, vb.x, vb.y, vb.z, vb.w};
            #pragma unroll
            for (int j = 0; j < 8; j++) {
                Oa[0][j] += p0 * vv[j];
                Oa[1][j] += p1 * vv[j];
                Oa[2][j] += p2 * vv[j];
                Oa[3][j] += p3 * vv[j];
            }
        }
    }

    #pragma unroll
    for (int i = 0; i < 4; i++) {
        float inv = 1.f / li[i];
        float* Orow = O + ((size_t)b * T_ + q0 + mr + i) * C_ + h * 64 + tx * 8;
        float o[8];
        #pragma unroll
        for (int j = 0; j < 8; j++) o[j] = Oa[i][j] * inv;
        *(float4*)&Orow[0] = *(float4*)&o[0];
        *(float4*)&Orow[4] = *(float4*)&o[4];
    }
}

// ---------------- launcher -------------------------------------------------
extern "C" void kernel_launch(void* const* d_in, const int* in_sizes, int n_in,
                              void* d_out, int out_size) {
    const float* x     = (const float*)d_in[0];
    const float* Wq    = (const float*)d_in[1];
    const float* Wk    = (const float*)d_in[2];
    const float* Wv    = (const float*)d_in[3];
    const float* Wproj = (const float*)d_in[4];
    const float* bproj = (const float*)d_in[5];
    const float* W1    = (const float*)d_in[6];
    const float* b1    = (const float*)d_in[7];
    const float* W2    = (const float*)d_in[8];
    const float* b2    = (const float*)d_in[9];
    const float* ln1s  = (const float*)d_in[10];
    const float* ln1b  = (const float*)d_in[11];
    const float* ln2s  = (const float*)d_in[12];
    const float* ln2b  = (const float*)d_in[13];
    float* out = (float*)d_out;

    float *h, *wq, *wk, *wv, *wpt, *w1t, *w2t, *q, *k, *v, *attn, *x1, *h2, *f1;
    cudaGetSymbolAddress((void**)&h,    g_h);
    cudaGetSymbolAddress((void**)&wq,   g_wq);
    cudaGetSymbolAddress((void**)&wk,   g_wk);
    cudaGetSymbolAddress((void**)&wv,   g_wv);
    cudaGetSymbolAddress((void**)&wpt,  g_wpt);
    cudaGetSymbolAddress((void**)&w1t,  g_w1t);
    cudaGetSymbolAddress((void**)&w2t,  g_w2t);
    cudaGetSymbolAddress((void**)&q,    g_q);
    cudaGetSymbolAddress((void**)&k,    g_k);
    cudaGetSymbolAddress((void**)&v,    g_v);
    cudaGetSymbolAddress((void**)&attn, g_attn);
    cudaGetSymbolAddress((void**)&x1,   g_x1);
    cudaGetSymbolAddress((void**)&h2,   g_h2);
    cudaGetSymbolAddress((void**)&f1,   g_f1);

    const int ATT_SMEM = ATT_SMEM_FLOATS * (int)sizeof(float);
    cudaFuncSetAttribute(attn_kernel,
                         cudaFuncAttributeMaxDynamicSharedMemorySize, ATT_SMEM);

    dim3 tb(32, 8);

    // LN1
    ln_kernel<<<BT, 256>>>(x, ln1s, ln1b, h);

    // weight transposes into [N,K] layouts
    transpose_k<<<dim3(2, 32, 16), tb>>>(Wq, wq, C_, 64, (long)C_ * 64, (long)64 * C_);
    transpose_k<<<dim3(2, 32, 16), tb>>>(Wk, wk, C_, 64, (long)C_ * 64, (long)64 * C_);
    transpose_k<<<dim3(2, 32, 16), tb>>>(Wv, wv, C_, 64, (long)C_ * 64, (long)64 * C_);
    transpose_k<<<dim3(32, 32, 1),  tb>>>(Wproj, wpt, C_, C_, 0, 0);
    transpose_k<<<dim3(128, 32, 1), tb>>>(W1, w1t, C_, FF, 0, 0);
    transpose_k<<<dim3(32, 128, 1), tb>>>(W2, w2t, FF, C_, 0, 0);

    // QKV projections (tf32 mma.sync)
    dim3 g1(C_ / 128, BT / 128);
    mma_gemm<0><<<g1, 256>>>(h, wq, nullptr, nullptr, q, BT, C_, C_);
    mma_gemm<0><<<g1, 256>>>(h, wk, nullptr, nullptr, k, BT, C_, C_);
    mma_gemm<0><<<g1, 256>>>(h, wv, nullptr, nullptr, v, BT, C_, C_);

    // attention
    attn_kernel<<<dim3(T_ / 128, B_ * H_), 256, ATT_SMEM>>>(q, k, v, attn);

    // out proj + residual
    mma_gemm<0><<<g1, 256>>>(attn, wpt, bproj, x, x1, BT, C_, C_);

    // LN2
    ln_kernel<<<BT, 256>>>(x1, ln2s, ln2b, h2);

    // MLP
    mma_gemm<1><<<dim3(FF / 128, BT / 128), 256>>>(h2, w1t, b1, nullptr, f1, BT, FF, C_);
    mma_gemm<0><<<g1, 256>>>(f1, w2t, b2, x1, out, BT, C_, FF);
}

// round 5
// speedup vs baseline: 2.6251x; 1.5081x over previous
#include <cuda_runtime.h>
#include <cuda_fp16.h>
#include <cstdint>

// Problem constants
#define B_ 2
#define T_ 2048
#define C_ 1024
#define H_ 16
#define D_ 64
#define BT 4096          // B_*T_
#define FF 4096          // 4*C_

// ---------------- scratch (static device globals; no allocation) -----------
__device__ float g_h   [BT * C_];   // LN1 output
__device__ float g_wq  [C_ * C_];   // Wq^T packed: [N=H*D, K=C]
__device__ float g_wk  [C_ * C_];
__device__ float g_wv  [C_ * C_];
__device__ float g_wpt [C_ * C_];   // Wproj^T [N=C, K=C]
__device__ float g_w1t [C_ * FF];   // W1^T [N=FF, K=C]
__device__ float g_w2t [C_ * FF];   // W2^T [N=C, K=FF]
__device__ float g_q   [BT * C_];   // [B,T,H*D]
__device__ float g_k   [BT * C_];
__device__ float g_v   [BT * C_];
__device__ float g_attn[BT * C_];   // concat heads
__device__ float g_x1  [BT * C_];   // x + attn@Wproj + bproj
__device__ float g_h2  [BT * C_];   // LN2 output
__device__ float g_f1  [BT * FF];   // relu(h2@W1+b1)

// tf32 destination is a .b32 register in PTX -> "=r" constraint
__device__ __forceinline__ float to_tf32(float x) {
    uint32_t r;
    asm("cvt.rna.tf32.f32 %0, %1;" : "=r"(r) : "f"(x));
    return __uint_as_float(r);
}
__device__ __forceinline__ uint32_t tf32b(float x) {
    uint32_t r;
    asm("cvt.rna.tf32.f32 %0, %1;" : "=r"(r) : "f"(x));
    return r;
}

// m16n8k8 tf32 mma (sm_80+ ISA; valid on sm_100)
__device__ __forceinline__ void mma8(float* c, const uint32_t* a, const uint32_t* b) {
    asm volatile(
        "mma.sync.aligned.m16n8k8.row.col.f32.tf32.tf32.f32 "
        "{%0,%1,%2,%3}, {%4,%5,%6,%7}, {%8,%9}, {%0,%1,%2,%3};"
        : "+f"(c[0]), "+f"(c[1]), "+f"(c[2]), "+f"(c[3])
        : "r"(a[0]), "r"(a[1]), "r"(a[2]), "r"(a[3]), "r"(b[0]), "r"(b[1]));
}

// packed half2 exp2 (one MUFU op for two exps)
__device__ __forceinline__ float2 exp2_f16x2(float t0, float t1) {
    __half2 hh = __floats2half2_rn(t0, t1);
    uint32_t hin = *reinterpret_cast<uint32_t*>(&hh);
    uint32_t hout;
    asm("ex2.approx.f16x2 %0, %1;" : "=r"(hout) : "r"(hin));
    __half2 he = *reinterpret_cast<__half2*>(&hout);
    return __half22float2(he);
}

// ---------------- LayerNorm: one block per row, C=1024 --------------------
__global__ void ln_kernel(const float* __restrict__ x,
                          const float* __restrict__ sc,
                          const float* __restrict__ bi,
                          float* __restrict__ out) {
    int row = blockIdx.x;
    const float* xr = x + (size_t)row * C_;
    float* orow = out + (size_t)row * C_;
    int tid = threadIdx.x;

    float4 v = ((const float4*)xr)[tid];
    float s  = v.x + v.y + v.z + v.w;
    float ss = v.x*v.x + v.y*v.y + v.z*v.z + v.w*v.w;
    #pragma unroll
    for (int o = 16; o; o >>= 1) {
        s  += __shfl_xor_sync(0xffffffffu, s,  o);
        ss += __shfl_xor_sync(0xffffffffu, ss, o);
    }
    __shared__ float sm[8], sm2[8];
    if ((tid & 31) == 0) { sm[tid >> 5] = s; sm2[tid >> 5] = ss; }
    __syncthreads();
    if (tid < 32) {
        float a  = (tid < 8) ? sm[tid]  : 0.f;
        float b2 = (tid < 8) ? sm2[tid] : 0.f;
        #pragma unroll
        for (int o = 4; o; o >>= 1) {
            a  += __shfl_xor_sync(0xffffffffu, a,  o);
            b2 += __shfl_xor_sync(0xffffffffu, b2, o);
        }
        if (tid == 0) { sm[0] = a; sm2[0] = b2; }
    }
    __syncthreads();
    float mean = sm[0] * (1.f / C_);
    float var  = sm2[0] * (1.f / C_) - mean * mean;
    float rstd = rsqrtf(var + 1e-6f);

    float4 sv = ((const float4*)sc)[tid];
    float4 bv = ((const float4*)bi)[tid];
    float4 o4;
    o4.x = (v.x - mean) * rstd * sv.x + bv.x;
    o4.y = (v.y - mean) * rstd * sv.y + bv.y;
    o4.z = (v.z - mean) * rstd * sv.z + bv.z;
    o4.w = (v.w - mean) * rstd * sv.w + bv.w;
    ((float4*)orow)[tid] = o4;
}

// ---------------- tiled transpose with batch (z) ---------------------------
__global__ void transpose_k(const float* __restrict__ src, float* __restrict__ dst,
                            int R, int Cc, long sstride, long dstride) {
    __shared__ float t[32][33];
    src += (long)blockIdx.z * sstride;
    dst += (long)blockIdx.z * dstride;
    int r0 = blockIdx.y * 32, c0 = blockIdx.x * 32;
    int x = threadIdx.x, y = threadIdx.y;
    #pragma unroll
    for (int i = 0; i < 32; i += 8)
        t[y + i][x] = src[(size_t)(r0 + y + i) * Cc + c0 + x];
    __syncthreads();
    #pragma unroll
    for (int i = 0; i < 32; i += 8)
        dst[(size_t)(c0 + y + i) * R + r0 + x] = t[x][y + i];
}

// ---------------- tf32 mma.sync GEMM (unchanged, validated R4) -------------
#define SA 20

template <int RELU>
__global__ void __launch_bounds__(256, 2) mma_gemm(
    const float* __restrict__ A, const float* __restrict__ Bt,
    const float* __restrict__ bias, const float* __restrict__ resid,
    float* __restrict__ Cc, int M, int N, int K)
{
    __shared__ float As[2][128 * SA];
    __shared__ float Bs[2][128 * SA];

    int tid  = threadIdx.x;
    int wid  = tid >> 5, lane = tid & 31;
    int g    = lane >> 2, r = lane & 3;
    int bm   = blockIdx.y, bn = blockIdx.x;
    int wm   = (wid & 1) * 64;
    int wn   = (wid >> 1) * 32;

    const float* Ab = A  + (size_t)bm * 128 * K;
    const float* Bb = Bt + (size_t)bn * 128 * K;

    float c[4][4][4];
    #pragma unroll
    for (int mt = 0; mt < 4; mt++)
        #pragma unroll
        for (int nt = 0; nt < 4; nt++)
            #pragma unroll
            for (int i = 0; i < 4; i++) c[mt][nt][i] = 0.f;

    float4 ra[2], rb[2];
    int row_[2], q_[2];
    #pragma unroll
    for (int i = 0; i < 2; i++) {
        int idx = tid + i * 256;
        row_[i] = idx >> 2;
        q_[i]   = (idx & 3) << 2;
    }

    #pragma unroll
    for (int i = 0; i < 2; i++) {
        ra[i] = *(const float4*)(Ab + (size_t)row_[i] * K + q_[i]);
        rb[i] = *(const float4*)(Bb + (size_t)row_[i] * K + q_[i]);
    }
    #pragma unroll
    for (int i = 0; i < 2; i++) {
        float4 a = ra[i], b = rb[i];
        a.x = to_tf32(a.x); a.y = to_tf32(a.y); a.z = to_tf32(a.z); a.w = to_tf32(a.w);
        b.x = to_tf32(b.x); b.y = to_tf32(b.y); b.z = to_tf32(b.z); b.w = to_tf32(b.w);
        *(float4*)&As[0][row_[i] * SA + q_[i]] = a;
        *(float4*)&Bs[0][row_[i] * SA + q_[i]] = b;
    }
    __syncthreads();

    int nch = K >> 4;
    for (int ch = 0; ch < nch; ch++) {
        int p = ch & 1;
        if (ch + 1 < nch) {
            int kt = (ch + 1) << 4;
            #pragma unroll
            for (int i = 0; i < 2; i++) {
                ra[i] = *(const float4*)(Ab + (size_t)row_[i] * K + kt + q_[i]);
                rb[i] = *(const float4*)(Bb + (size_t)row_[i] * K + kt + q_[i]);
            }
        }

        const float* Ap = As[p];
        const float* Bp = Bs[p];
        #pragma unroll
        for (int ks = 0; ks < 2; ks++) {
            int kk = ks * 8;
            uint32_t af[4][4], bf[4][2];
            #pragma unroll
            for (int mt = 0; mt < 4; mt++) {
                int m = wm + mt * 16 + g;
                af[mt][0] = __float_as_uint(Ap[(m    ) * SA + kk + r    ]);
                af[mt][1] = __float_as_uint(Ap[(m + 8) * SA + kk + r    ]);
                af[mt][2] = __float_as_uint(Ap[(m    ) * SA + kk + r + 4]);
                af[mt][3] = __float_as_uint(Ap[(m + 8) * SA + kk + r + 4]);
            }
            #pragma unroll
            for (int nt = 0; nt < 4; nt++) {
                int n = wn + nt * 8 + g;
                bf[nt][0] = __float_as_uint(Bp[n * SA + kk + r    ]);
                bf[nt][1] = __float_as_uint(Bp[n * SA + kk + r + 4]);
            }
            #pragma unroll
            for (int mt = 0; mt < 4; mt++)
                #pragma unroll
                for (int nt = 0; nt < 4; nt++)
                    mma8(c[mt][nt], af[mt], bf[nt]);
        }

        if (ch + 1 < nch) {
            int pn = p ^ 1;
            #pragma unroll
            for (int i = 0; i < 2; i++) {
                float4 a = ra[i], b = rb[i];
                a.x = to_tf32(a.x); a.y = to_tf32(a.y); a.z = to_tf32(a.z); a.w = to_tf32(a.w);
                b.x = to_tf32(b.x); b.y = to_tf32(b.y); b.z = to_tf32(b.z); b.w = to_tf32(b.w);
                *(float4*)&As[pn][row_[i] * SA + q_[i]] = a;
                *(float4*)&Bs[pn][row_[i] * SA + q_[i]] = b;
            }
        }
        __syncthreads();
    }

    #pragma unroll
    for (int mt = 0; mt < 4; mt++) {
        #pragma unroll
        for (int rr = 0; rr < 2; rr++) {
            int m = bm * 128 + wm + mt * 16 + g + rr * 8;
            float* Crow = Cc + (size_t)m * N + bn * 128;
            const float* Rrow = resid ? resid + (size_t)m * N + bn * 128 : nullptr;
            #pragma unroll
            for (int nt = 0; nt < 4; nt++) {
                int nc = wn + nt * 8 + 2 * r;
                float v0 = c[mt][nt][rr * 2 + 0];
                float v1 = c[mt][nt][rr * 2 + 1];
                if (bias)  { v0 += bias[bn * 128 + nc]; v1 += bias[bn * 128 + nc + 1]; }
                if (resid) { v0 += Rrow[nc]; v1 += Rrow[nc + 1]; }
                if (RELU)  { v0 = fmaxf(v0, 0.f); v1 = fmaxf(v1, 0.f); }
                float2 o2 = make_float2(v0, v1);
                *(float2*)&Crow[nc] = o2;
            }
        }
    }
}

// ---------------- tensor-core flash attention ------------------------------
// 128 q-rows per CTA (8 warps x 16 rows), 64-key tiles, D=64.
// S and PV via tf32 m16n8k8; softmax exp via ex2.approx.f16x2.
// SMEM strides chosen bank-conflict-free for fragment loads:
//   Ks stride 68: bank (4g+r) bijective; Vs stride 72: bank (8r+g) bijective;
//   Ps stride 68: bank (4g+r) bijective.
#define AT_KS 68
#define AT_VS 72
#define AT_PS 68
#define ATT_SMEM_BYTES ((64*AT_KS + 64*AT_VS + 128*AT_PS) * 4)   // 70656
#define LOG2E 1.4426950408889634f

__global__ void __launch_bounds__(256, 1) attn_mma(
    const float* __restrict__ Q, const float* __restrict__ K,
    const float* __restrict__ V, float* __restrict__ O)
{
    extern __shared__ float smf[];
    float* Ks = smf;
    float* Vs = Ks + 64 * AT_KS;
    float* Ps = Vs + 64 * AT_VS;

    int tid = threadIdx.x;
    int wid = tid >> 5, lane = tid & 31;
    int g = lane >> 2, r = lane & 3;
    int b = blockIdx.y >> 4, h = blockIdx.y & 15;
    int q0 = blockIdx.x * 128;
    int m0 = wid * 16;

    const float* Qb = Q + (size_t)b * T_ * C_ + h * 64;
    const float* Kb = K + (size_t)b * T_ * C_ + h * 64;
    const float* Vb = V + (size_t)b * T_ * C_ + h * 64;

    int row0 = q0 + m0 + g;     // this lane's first q-row
    int row1 = row0 + 8;        // second q-row

    // Q fragments in registers for the whole KV loop (tf32-rounded)
    uint32_t qa[8][4];
    #pragma unroll
    for (int kk = 0; kk < 8; kk++) {
        int d0 = kk * 8;
        qa[kk][0] = tf32b(Qb[(size_t)row0 * C_ + d0 + r    ]);
        qa[kk][1] = tf32b(Qb[(size_t)row1 * C_ + d0 + r    ]);
        qa[kk][2] = tf32b(Qb[(size_t)row0 * C_ + d0 + r + 4]);
        qa[kk][3] = tf32b(Qb[(size_t)row1 * C_ + d0 + r + 4]);
    }

    float oa[8][4];
    #pragma unroll
    for (int nt = 0; nt < 8; nt++)
        #pragma unroll
        for (int i = 0; i < 4; i++) oa[nt][i] = 0.f;
    float mi0 = -1e30f, mi1 = -1e30f, li0 = 0.f, li1 = 0.f;

    float* Pw = Ps + m0 * AT_PS;   // warp-private P rows

    int ntiles = (q0 >> 6) + 2;
    for (int kt = 0; kt < ntiles; kt++) {
        int k0 = kt << 6;
        __syncthreads();    // all warps done reading Ks/Vs of prev tile
        // cooperative K/V tile load (tf32-rounded), coalesced float4
        for (int i = tid; i < 64 * 16; i += 256) {
            int rr = i >> 4, d4 = (i & 15) << 2;
            float4 kv = *(const float4*)(Kb + (size_t)(k0 + rr) * C_ + d4);
            kv.x = to_tf32(kv.x); kv.y = to_tf32(kv.y);
            kv.z = to_tf32(kv.z); kv.w = to_tf32(kv.w);
            *(float4*)&Ks[rr * AT_KS + d4] = kv;
            float4 vv = *(const float4*)(Vb + (size_t)(k0 + rr) * C_ + d4);
            vv.x = to_tf32(vv.x); vv.y = to_tf32(vv.y);
            vv.z = to_tf32(vv.z); vv.w = to_tf32(vv.w);
            *(float4*)&Vs[rr * AT_VS + d4] = vv;
        }
        __syncthreads();

        // ---- S = Q K^T (warp rows m0..m0+15, cols 0..63 of this tile) ----
        float sc[8][4];
        #pragma unroll
        for (int nt = 0; nt < 8; nt++)
            #pragma unroll
            for (int i = 0; i < 4; i++) sc[nt][i] = 0.f;
        #pragma unroll
        for (int kk = 0; kk < 8; kk++) {
            int d0 = kk * 8;
            #pragma unroll
            for (int nt = 0; nt < 8; nt++) {
                uint32_t bf[2];
                bf[0] = __float_as_uint(Ks[(nt * 8 + g) * AT_KS + d0 + r    ]);
                bf[1] = __float_as_uint(Ks[(nt * 8 + g) * AT_KS + d0 + r + 4]);
                mma8(sc[nt], qa[kk], bf);
            }
        }

        // ---- scale + causal mask + row max ----
        float mx0 = -1e30f, mx1 = -1e30f;
        #pragma unroll
        for (int nt = 0; nt < 8; nt++) {
            int c0 = k0 + nt * 8 + 2 * r;
            int c1 = c0 + 1;
            sc[nt][0] = (c0 <= row0) ? sc[nt][0] * 0.03125f : -1e30f;
            sc[nt][1] = (c1 <= row0) ? sc[nt][1] * 0.03125f : -1e30f;
            sc[nt][2] = (c0 <= row1) ? sc[nt][2] * 0.03125f : -1e30f;
            sc[nt][3] = (c1 <= row1) ? sc[nt][3] * 0.03125f : -1e30f;
            mx0 = fmaxf(mx0, fmaxf(sc[nt][0], sc[nt][1]));
            mx1 = fmaxf(mx1, fmaxf(sc[nt][2], sc[nt][3]));
        }
        mx0 = fmaxf(mx0, __shfl_xor_sync(0xffffffffu, mx0, 1));
        mx0 = fmaxf(mx0, __shfl_xor_sync(0xffffffffu, mx0, 2));
        mx1 = fmaxf(mx1, __shfl_xor_sync(0xffffffffu, mx1, 1));
        mx1 = fmaxf(mx1, __shfl_xor_sync(0xffffffffu, mx1, 2));

        float mn0 = fmaxf(mi0, mx0), mn1 = fmaxf(mi1, mx1);
        float corr0 = __expf(mi0 - mn0);
        float corr1 = __expf(mi1 - mn1);

        // ---- exp (f16x2 packed) + write P to warp-private smem ----
        float s0 = 0.f, s1 = 0.f;
        #pragma unroll
        for (int nt = 0; nt < 8; nt++) {
            float2 p01 = exp2_f16x2((sc[nt][0] - mn0) * LOG2E,
                                    (sc[nt][1] - mn0) * LOG2E);
            float2 p23 = exp2_f16x2((sc[nt][2] - mn1) * LOG2E,
                                    (sc[nt][3] - mn1) * LOG2E);
            p01.x = to_tf32(p01.x); p01.y = to_tf32(p01.y);
            p23.x = to_tf32(p23.x); p23.y = to_tf32(p23.y);
            s0 += p01.x + p01.y;
            s1 += p23.x + p23.y;
            *(float2*)&Pw[(g    ) * AT_PS + nt * 8 + 2 * r] = p01;
            *(float2*)&Pw[(g + 8) * AT_PS + nt * 8 + 2 * r] = p23;
        }
        s0 += __shfl_xor_sync(0xffffffffu, s0, 1);
        s0 += __shfl_xor_sync(0xffffffffu, s0, 2);
        s1 += __shfl_xor_sync(0xffffffffu, s1, 1);
        s1 += __shfl_xor_sync(0xffffffffu, s1, 2);
        li0 = li0 * corr0 + s0;
        li1 = li1 * corr1 + s1;
        mi0 = mn0; mi1 = mn1;

        // rescale O accumulators
        #pragma unroll
        for (int nt = 0; nt < 8; nt++) {
            oa[nt][0] *= corr0; oa[nt][1] *= corr0;
            oa[nt][2] *= corr1; oa[nt][3] *= corr1;
        }
        __syncwarp();

        // ---- O += P V ----
        #pragma unroll
        for (int kk = 0; kk < 8; kk++) {
            int s8 = kk * 8;
            uint32_t pa[4];
            pa[0] = __float_as_uint(Pw[(g    ) * AT_PS + s8 + r    ]);
            pa[1] = __float_as_uint(Pw[(g + 8) * AT_PS + s8 + r    ]);
            pa[2] = __float_as_uint(Pw[(g    ) * AT_PS + s8 + r + 4]);
            pa[3] = __float_as_uint(Pw[(g + 8) * AT_PS + s8 + r + 4]);
            #pragma unroll
            for (int nt = 0; nt < 8; nt++) {
                uint32_t bf[2];
                bf[0] = __float_as_uint(Vs[(s8 + r    ) * AT_VS + nt * 8 + g]);
                bf[1] = __float_as_uint(Vs[(s8 + r + 4) * AT_VS + nt * 8 + g]);
                mma8(oa[nt], pa, bf);
            }
        }
    }

    // ---- normalize + write (concat-heads layout) ----
    float inv0 = 1.f / li0, inv1 = 1.f / li1;
    float* Ob = O + (size_t)b * T_ * C_ + h * 64;
    #pragma unroll
    for (int nt = 0; nt < 8; nt++) {
        int cc = nt * 8 + 2 * r;
        float2 o0 = make_float2(oa[nt][0] * inv0, oa[nt][1] * inv0);
        float2 o1 = make_float2(oa[nt][2] * inv1, oa[nt][3] * inv1);
        *(float2*)&Ob[(size_t)row0 * C_ + cc] = o0;
        *(float2*)&Ob[(size_t)row1 * C_ + cc] = o1;
    }
}

// ---------------- launcher -------------------------------------------------
extern "C" void kernel_launch(void* const* d_in, const int* in_sizes, int n_in,
                              void* d_out, int out_size) {
    const float* x     = (const float*)d_in[0];
    const float* Wq    = (const float*)d_in[1];
    const float* Wk    = (const float*)d_in[2];
    const float* Wv    = (const float*)d_in[3];
    const float* Wproj = (const float*)d_in[4];
    const float* bproj = (const float*)d_in[5];
    const float* W1    = (const float*)d_in[6];
    const float* b1    = (const float*)d_in[7];
    const float* W2    = (const float*)d_in[8];
    const float* b2    = (const float*)d_in[9];
    const float* ln1s  = (const float*)d_in[10];
    const float* ln1b  = (const float*)d_in[11];
    const float* ln2s  = (const float*)d_in[12];
    const float* ln2b  = (const float*)d_in[13];
    float* out = (float*)d_out;

    float *h, *wq, *wk, *wv, *wpt, *w1t, *w2t, *q, *k, *v, *attn, *x1, *h2, *f1;
    cudaGetSymbolAddress((void**)&h,    g_h);
    cudaGetSymbolAddress((void**)&wq,   g_wq);
    cudaGetSymbolAddress((void**)&wk,   g_wk);
    cudaGetSymbolAddress((void**)&wv,   g_wv);
    cudaGetSymbolAddress((void**)&wpt,  g_wpt);
    cudaGetSymbolAddress((void**)&w1t,  g_w1t);
    cudaGetSymbolAddress((void**)&w2t,  g_w2t);
    cudaGetSymbolAddress((void**)&q,    g_q);
    cudaGetSymbolAddress((void**)&k,    g_k);
    cudaGetSymbolAddress((void**)&v,    g_v);
    cudaGetSymbolAddress((void**)&attn, g_attn);
    cudaGetSymbolAddress((void**)&x1,   g_x1);
    cudaGetSymbolAddress((void**)&h2,   g_h2);
    cudaGetSymbolAddress((void**)&f1,   g_f1);

    cudaFuncSetAttribute(attn_mma,
                         cudaFuncAttributeMaxDynamicSharedMemorySize, ATT_SMEM_BYTES);

    dim3 tb(32, 8);

    // LN1
    ln_kernel<<<BT, 256>>>(x, ln1s, ln1b, h);

    // weight transposes into [N,K] layouts
    transpose_k<<<dim3(2, 32, 16), tb>>>(Wq, wq, C_, 64, (long)C_ * 64, (long)64 * C_);
    transpose_k<<<dim3(2, 32, 16), tb>>>(Wk, wk, C_, 64, (long)C_ * 64, (long)64 * C_);
    transpose_k<<<dim3(2, 32, 16), tb>>>(Wv, wv, C_, 64, (long)C_ * 64, (long)64 * C_);
    transpose_k<<<dim3(32, 32, 1),  tb>>>(Wproj, wpt, C_, C_, 0, 0);
    transpose_k<<<dim3(128, 32, 1), tb>>>(W1, w1t, C_, FF, 0, 0);
    transpose_k<<<dim3(32, 128, 1), tb>>>(W2, w2t, FF, C_, 0, 0);

    // QKV projections (tf32 mma.sync)
    dim3 g1(C_ / 128, BT / 128);
    mma_gemm<0><<<g1, 256>>>(h, wq, nullptr, nullptr, q, BT, C_, C_);
    mma_gemm<0><<<g1, 256>>>(h, wk, nullptr, nullptr, k, BT, C_, C_);
    mma_gemm<0><<<g1, 256>>>(h, wv, nullptr, nullptr, v, BT, C_, C_);

    // attention (tensor-core flash)
    attn_mma<<<dim3(T_ / 128, B_ * H_), 256, ATT_SMEM_BYTES>>>(q, k, v, attn);

    // out proj + residual
    mma_gemm<0><<<g1, 256>>>(attn, wpt, bproj, x, x1, BT, C_, C_);

    // LN2
    ln_kernel<<<BT, 256>>>(x1, ln2s, ln2b, h2);

    // MLP
    mma_gemm<1><<<dim3(FF / 128, BT / 128), 256>>>(h2, w1t, b1, nullptr, f1, BT, FF, C_);
    mma_gemm<0><<<g1, 256>>>(f1, w2t, b2, x1, out, BT, C_, FF);
}

// round 6
// speedup vs baseline: 3.4043x; 1.2968x over previous
#include <cuda_runtime.h>
#include <cuda_fp16.h>
#include <cstdint>

// Problem constants
#define B_ 2
#define T_ 2048
#define C_ 1024
#define H_ 16
#define D_ 64
#define BT 4096          // B_*T_
#define FF 4096          // 4*C_
#define C3 3072          // 3*C_

// ---------------- scratch (static device globals; no allocation) -----------
__device__ float g_h   [BT * C_];   // LN1 output (tf32-rounded)
__device__ float g_wqkv[C_ * C3];   // packed+rounded QKV weights [K=C, N=3C]
__device__ float g_wp  [C_ * C_];   // rounded Wproj [K,N]
__device__ float g_w1  [C_ * FF];   // rounded W1 [K,N]
__device__ float g_w2  [FF * C_];   // rounded W2 [K,N]
__device__ float g_qkv [BT * C3];   // fused q|k|v  [B,T, 3C] (rounded)
__device__ float g_attn[BT * C_];   // concat heads (rounded)
__device__ float g_x1  [BT * C_];   // x + attn@Wproj + bproj (exact fp32)
__device__ float g_h2  [BT * C_];   // LN2 output (rounded)
__device__ float g_f1  [BT * FF];   // relu(h2@W1+b1) (rounded)

// tf32 helpers
__device__ __forceinline__ float to_tf32(float x) {
    uint32_t r;
    asm("cvt.rna.tf32.f32 %0, %1;" : "=r"(r) : "f"(x));
    return __uint_as_float(r);
}

// m16n8k8 tf32 mma
__device__ __forceinline__ void mma8(float* c, const uint32_t* a, const uint32_t* b) {
    asm volatile(
        "mma.sync.aligned.m16n8k8.row.col.f32.tf32.tf32.f32 "
        "{%0,%1,%2,%3}, {%4,%5,%6,%7}, {%8,%9}, {%0,%1,%2,%3};"
        : "+f"(c[0]), "+f"(c[1]), "+f"(c[2]), "+f"(c[3])
        : "r"(a[0]), "r"(a[1]), "r"(a[2]), "r"(a[3]), "r"(b[0]), "r"(b[1]));
}

// packed half2 exp2
__device__ __forceinline__ float2 exp2_f16x2(float t0, float t1) {
    __half2 hh = __floats2half2_rn(t0, t1);
    uint32_t hin = *reinterpret_cast<uint32_t*>(&hh);
    uint32_t hout;
    asm("ex2.approx.f16x2 %0, %1;" : "=r"(hout) : "r"(hin));
    __half2 he = *reinterpret_cast<__half2*>(&hout);
    return __half22float2(he);
}

__device__ __forceinline__ uint32_t smem_u32(const void* p) {
    uint32_t a;
    asm("{ .reg .u64 t; cvta.to.shared.u64 t, %1; cvt.u32.u64 %0, t; }"
        : "=r"(a) : "l"(p));
    return a;
}
#define CP16(dst, src) \
    asm volatile("cp.async.cg.shared.global [%0], [%1], 16;" \
                 :: "r"(dst), "l"(src) : "memory")
#define CP_COMMIT() asm volatile("cp.async.commit_group;" ::: "memory")
#define CP_WAIT1()  asm volatile("cp.async.wait_group 1;"  ::: "memory")

// ---------------- LayerNorm (output tf32-rounded) --------------------------
__global__ void ln_kernel(const float* __restrict__ x,
                          const float* __restrict__ sc,
                          const float* __restrict__ bi,
                          float* __restrict__ out) {
    int row = blockIdx.x;
    const float* xr = x + (size_t)row * C_;
    float* orow = out + (size_t)row * C_;
    int tid = threadIdx.x;

    float4 v = ((const float4*)xr)[tid];
    float s  = v.x + v.y + v.z + v.w;
    float ss = v.x*v.x + v.y*v.y + v.z*v.z + v.w*v.w;
    #pragma unroll
    for (int o = 16; o; o >>= 1) {
        s  += __shfl_xor_sync(0xffffffffu, s,  o);
        ss += __shfl_xor_sync(0xffffffffu, ss, o);
    }
    __shared__ float sm[8], sm2[8];
    if ((tid & 31) == 0) { sm[tid >> 5] = s; sm2[tid >> 5] = ss; }
    __syncthreads();
    if (tid < 32) {
        float a  = (tid < 8) ? sm[tid]  : 0.f;
        float b2 = (tid < 8) ? sm2[tid] : 0.f;
        #pragma unroll
        for (int o = 4; o; o >>= 1) {
            a  += __shfl_xor_sync(0xffffffffu, a,  o);
            b2 += __shfl_xor_sync(0xffffffffu, b2, o);
        }
        if (tid == 0) { sm[0] = a; sm2[0] = b2; }
    }
    __syncthreads();
    float mean = sm[0] * (1.f / C_);
    float var  = sm2[0] * (1.f / C_) - mean * mean;
    float rstd = rsqrtf(var + 1e-6f);

    float4 sv = ((const float4*)sc)[tid];
    float4 bv = ((const float4*)bi)[tid];
    float4 o4;
    o4.x = to_tf32((v.x - mean) * rstd * sv.x + bv.x);
    o4.y = to_tf32((v.y - mean) * rstd * sv.y + bv.y);
    o4.z = to_tf32((v.z - mean) * rstd * sv.z + bv.z);
    o4.w = to_tf32((v.w - mean) * rstd * sv.w + bv.w);
    ((float4*)orow)[tid] = o4;
}

// ---------------- weight prep ----------------------------------------------
// pack per-head Wq/Wk/Wv [H,C,D] -> [K=C, N=3C], tf32-rounded
__global__ void pack_qkvw(const float* __restrict__ Wq,
                          const float* __restrict__ Wk,
                          const float* __restrict__ Wv,
                          float* __restrict__ out) {
    int idx = blockIdx.x * 256 + threadIdx.x;       // C_*C3 total
    int c = idx / C3, n = idx % C3;
    const float* W = (n < C_) ? Wq : ((n < 2 * C_) ? Wk : Wv);
    int inner = n & (C_ - 1);
    int hh = inner >> 6, d = inner & 63;
    out[idx] = to_tf32(W[((size_t)hh * C_ + c) * 64 + d]);
}

// elementwise tf32 round-copy (float4)
__global__ void round_copy(const float* __restrict__ src, float* __restrict__ dst) {
    int i = blockIdx.x * 256 + threadIdx.x;
    float4 v = ((const float4*)src)[i];
    v.x = to_tf32(v.x); v.y = to_tf32(v.y);
    v.z = to_tf32(v.z); v.w = to_tf32(v.w);
    ((float4*)dst)[i] = v;
}

// ---------------- tf32 mma.sync GEMM v2 (cp.async, direct [K,N] B) ---------
// C[M,N] = A[M,K] @ B[K,N] (+bias)(+resid)(relu)(round-out)
// Inputs pre-rounded to tf32. CTA 128x128, BK=16, 3-stage cp.async pipeline.
// SMEM per stage: A 128x20 fl + B 16x136 fl.
#define G_SA 20
#define G_SB 136
#define G_STG_FL (128 * G_SA + 16 * G_SB)   // 4736 floats
#define G_STG_BY (G_STG_FL * 4)             // 18944 bytes
#define G_BOFF   (128 * G_SA)               // B offset within stage (floats)
#define G_SMEM   (3 * G_STG_BY)             // 56832 bytes

template <int RELU, int ROUND>
__global__ void __launch_bounds__(256, 2) mma_gemm(
    const float* __restrict__ A, const float* __restrict__ B,
    const float* __restrict__ bias, const float* __restrict__ resid,
    float* __restrict__ Cc, int M, int N, int K)
{
    extern __shared__ float smf[];
    uint32_t sbase = smem_u32(smf);

    int tid  = threadIdx.x;
    int wid  = tid >> 5, lane = tid & 31;
    int g    = lane >> 2, r = lane & 3;
    int bm   = blockIdx.y, bn = blockIdx.x;
    int wm   = (wid & 1) * 64;
    int wn   = (wid >> 1) * 32;

    const float* Ab = A + (size_t)bm * 128 * K;
    const float* Bb = B + bn * 128;

    // per-thread cp.async source/dest mapping
    int ar = tid >> 2, ac = (tid & 3) << 2;     // A rows ar, ar+64; col seg ac
    int br = tid >> 5, bc = (tid & 31) << 2;    // B rows br, br+8;  col seg bc
    const float* Asrc = Ab + (size_t)ar * K + ac;
    const float* Bsrc = Bb + (size_t)br * N + bc;
    uint32_t ad0 = sbase + (uint32_t)(ar * G_SA + ac) * 4;
    uint32_t ad1 = ad0 + 64 * G_SA * 4;
    uint32_t bd0 = sbase + (uint32_t)(G_BOFF + br * G_SB + bc) * 4;
    uint32_t bd1 = bd0 + 8 * G_SB * 4;

    float c[4][4][4];
    #pragma unroll
    for (int mt = 0; mt < 4; mt++)
        #pragma unroll
        for (int nt = 0; nt < 4; nt++)
            #pragma unroll
            for (int i = 0; i < 4; i++) c[mt][nt][i] = 0.f;

    int nch = K >> 4;

    // prologue: stages 0,1
    {
        CP16(ad0, Asrc);  CP16(ad1, Asrc + (size_t)64 * K);
        CP16(bd0, Bsrc);  CP16(bd1, Bsrc + (size_t)8 * N);
        CP_COMMIT();
        uint32_t s1 = G_STG_BY;
        CP16(ad0 + s1, Asrc + 16);  CP16(ad1 + s1, Asrc + (size_t)64 * K + 16);
        CP16(bd0 + s1, Bsrc + (size_t)16 * N);
        CP16(bd1 + s1, Bsrc + (size_t)24 * N);
        CP_COMMIT();
    }

    for (int ch = 0; ch < nch; ch++) {
        int st = ch % 3;
        CP_WAIT1();
        __syncthreads();

        const float* Ap = smf + st * G_STG_FL;
        const float* Bp = Ap + G_BOFF;
        #pragma unroll
        for (int ks = 0; ks < 2; ks++) {
            int kk = ks * 8;
            uint32_t af[4][4], bf[4][2];
            #pragma unroll
            for (int mt = 0; mt < 4; mt++) {
                int m = wm + mt * 16 + g;
                af[mt][0] = __float_as_uint(Ap[(m    ) * G_SA + kk + r    ]);
                af[mt][1] = __float_as_uint(Ap[(m + 8) * G_SA + kk + r    ]);
                af[mt][2] = __float_as_uint(Ap[(m    ) * G_SA + kk + r + 4]);
                af[mt][3] = __float_as_uint(Ap[(m + 8) * G_SA + kk + r + 4]);
            }
            #pragma unroll
            for (int nt = 0; nt < 4; nt++) {
                int n = wn + nt * 8 + g;
                bf[nt][0] = __float_as_uint(Bp[(kk + r    ) * G_SB + n]);
                bf[nt][1] = __float_as_uint(Bp[(kk + r + 4) * G_SB + n]);
            }
            #pragma unroll
            for (int mt = 0; mt < 4; mt++)
                #pragma unroll
                for (int nt = 0; nt < 4; nt++)
                    mma8(c[mt][nt], af[mt], bf[nt]);
        }

        int nc2 = ch + 2;
        if (nc2 < nch) {
            int kt = nc2 << 4;
            uint32_t so = (uint32_t)(nc2 % 3) * G_STG_BY;
            CP16(ad0 + so, Asrc + kt);
            CP16(ad1 + so, Asrc + (size_t)64 * K + kt);
            CP16(bd0 + so, Bsrc + (size_t)kt * N);
            CP16(bd1 + so, Bsrc + (size_t)(kt + 8) * N);
        }
        CP_COMMIT();
    }

    // epilogue
    #pragma unroll
    for (int mt = 0; mt < 4; mt++) {
        #pragma unroll
        for (int rr = 0; rr < 2; rr++) {
            int m = bm * 128 + wm + mt * 16 + g + rr * 8;
            float* Crow = Cc + (size_t)m * N + bn * 128;
            const float* Rrow = resid ? resid + (size_t)m * N + bn * 128 : nullptr;
            #pragma unroll
            for (int nt = 0; nt < 4; nt++) {
                int nc = wn + nt * 8 + 2 * r;
                float v0 = c[mt][nt][rr * 2 + 0];
                float v1 = c[mt][nt][rr * 2 + 1];
                if (bias)  { v0 += bias[bn * 128 + nc]; v1 += bias[bn * 128 + nc + 1]; }
                if (resid) { v0 += Rrow[nc]; v1 += Rrow[nc + 1]; }
                if (RELU)  { v0 = fmaxf(v0, 0.f); v1 = fmaxf(v1, 0.f); }
                if (ROUND) { v0 = to_tf32(v0); v1 = to_tf32(v1); }
                float2 o2 = make_float2(v0, v1);
                *(float2*)&Crow[nc] = o2;
            }
        }
    }
}

// ---------------- tensor-core flash attention (QKV fused input) ------------
// Q/K/V are column sections of g_qkv [BT, 3C], row stride 3C, pre-rounded.
#define AT_KS 68
#define AT_VS 72
#define AT_PS 68
#define ATT_SMEM_BYTES ((64*AT_KS + 64*AT_VS + 128*AT_PS) * 4)
#define LOG2E 1.4426950408889634f

__global__ void __launch_bounds__(256, 1) attn_mma(
    const float* __restrict__ QKV, float* __restrict__ O)
{
    extern __shared__ float smf[];
    float* Ks = smf;
    float* Vs = Ks + 64 * AT_KS;
    float* Ps = Vs + 64 * AT_VS;

    int tid = threadIdx.x;
    int wid = tid >> 5, lane = tid & 31;
    int g = lane >> 2, r = lane & 3;
    int b = blockIdx.y >> 4, h = blockIdx.y & 15;
    int q0 = blockIdx.x * 128;
    int m0 = wid * 16;

    const float* Qb = QKV + (size_t)b * T_ * C3 + h * 64;
    const float* Kb = Qb + C_;
    const float* Vb = Qb + 2 * C_;

    int row0 = q0 + m0 + g;
    int row1 = row0 + 8;

    uint32_t qa[8][4];
    #pragma unroll
    for (int kk = 0; kk < 8; kk++) {
        int d0 = kk * 8;
        qa[kk][0] = __float_as_uint(Qb[(size_t)row0 * C3 + d0 + r    ]);
        qa[kk][1] = __float_as_uint(Qb[(size_t)row1 * C3 + d0 + r    ]);
        qa[kk][2] = __float_as_uint(Qb[(size_t)row0 * C3 + d0 + r + 4]);
        qa[kk][3] = __float_as_uint(Qb[(size_t)row1 * C3 + d0 + r + 4]);
    }

    float oa[8][4];
    #pragma unroll
    for (int nt = 0; nt < 8; nt++)
        #pragma unroll
        for (int i = 0; i < 4; i++) oa[nt][i] = 0.f;
    float mi0 = -1e30f, mi1 = -1e30f, li0 = 0.f, li1 = 0.f;

    float* Pw = Ps + m0 * AT_PS;

    int ntiles = (q0 >> 6) + 2;
    for (int kt = 0; kt < ntiles; kt++) {
        int k0 = kt << 6;
        __syncthreads();
        for (int i = tid; i < 64 * 16; i += 256) {
            int rr = i >> 4, d4 = (i & 15) << 2;
            float4 kv = *(const float4*)(Kb + (size_t)(k0 + rr) * C3 + d4);
            *(float4*)&Ks[rr * AT_KS + d4] = kv;
            float4 vv = *(const float4*)(Vb + (size_t)(k0 + rr) * C3 + d4);
            *(float4*)&Vs[rr * AT_VS + d4] = vv;
        }
        __syncthreads();

        float sc[8][4];
        #pragma unroll
        for (int nt = 0; nt < 8; nt++)
            #pragma unroll
            for (int i = 0; i < 4; i++) sc[nt][i] = 0.f;
        #pragma unroll
        for (int kk = 0; kk < 8; kk++) {
            int d0 = kk * 8;
            #pragma unroll
            for (int nt = 0; nt < 8; nt++) {
                uint32_t bfr[2];
                bfr[0] = __float_as_uint(Ks[(nt * 8 + g) * AT_KS + d0 + r    ]);
                bfr[1] = __float_as_uint(Ks[(nt * 8 + g) * AT_KS + d0 + r + 4]);
                mma8(sc[nt], qa[kk], bfr);
            }
        }

        float mx0 = -1e30f, mx1 = -1e30f;
        #pragma unroll
        for (int nt = 0; nt < 8; nt++) {
            int c0 = k0 + nt * 8 + 2 * r;
            int c1 = c0 + 1;
            sc[nt][0] = (c0 <= row0) ? sc[nt][0] * 0.03125f : -1e30f;
            sc[nt][1] = (c1 <= row0) ? sc[nt][1] * 0.03125f : -1e30f;
            sc[nt][2] = (c0 <= row1) ? sc[nt][2] * 0.03125f : -1e30f;
            sc[nt][3] = (c1 <= row1) ? sc[nt][3] * 0.03125f : -1e30f;
            mx0 = fmaxf(mx0, fmaxf(sc[nt][0], sc[nt][1]));
            mx1 = fmaxf(mx1, fmaxf(sc[nt][2], sc[nt][3]));
        }
        mx0 = fmaxf(mx0, __shfl_xor_sync(0xffffffffu, mx0, 1));
        mx0 = fmaxf(mx0, __shfl_xor_sync(0xffffffffu, mx0, 2));
        mx1 = fmaxf(mx1, __shfl_xor_sync(0xffffffffu, mx1, 1));
        mx1 = fmaxf(mx1, __shfl_xor_sync(0xffffffffu, mx1, 2));

        float mn0 = fmaxf(mi0, mx0), mn1 = fmaxf(mi1, mx1);
        float corr0 = __expf(mi0 - mn0);
        float corr1 = __expf(mi1 - mn1);

        float s0 = 0.f, s1 = 0.f;
        #pragma unroll
        for (int nt = 0; nt < 8; nt++) {
            float2 p01 = exp2_f16x2((sc[nt][0] - mn0) * LOG2E,
                                    (sc[nt][1] - mn0) * LOG2E);
            float2 p23 = exp2_f16x2((sc[nt][2] - mn1) * LOG2E,
                                    (sc[nt][3] - mn1) * LOG2E);
            p01.x = to_tf32(p01.x); p01.y = to_tf32(p01.y);
            p23.x = to_tf32(p23.x); p23.y = to_tf32(p23.y);
            s0 += p01.x + p01.y;
            s1 += p23.x + p23.y;
            *(float2*)&Pw[(g    ) * AT_PS + nt * 8 + 2 * r] = p01;
            *(float2*)&Pw[(g + 8) * AT_PS + nt * 8 + 2 * r] = p23;
        }
        s0 += __shfl_xor_sync(0xffffffffu, s0, 1);
        s0 += __shfl_xor_sync(0xffffffffu, s0, 2);
        s1 += __shfl_xor_sync(0xffffffffu, s1, 1);
        s1 += __shfl_xor_sync(0xffffffffu, s1, 2);
        li0 = li0 * corr0 + s0;
        li1 = li1 * corr1 + s1;
        mi0 = mn0; mi1 = mn1;

        #pragma unroll
        for (int nt = 0; nt < 8; nt++) {
            oa[nt][0] *= corr0; oa[nt][1] *= corr0;
            oa[nt][2] *= corr1; oa[nt][3] *= corr1;
        }
        __syncwarp();

        #pragma unroll
        for (int kk = 0; kk < 8; kk++) {
            int s8 = kk * 8;
            uint32_t pa[4];
            pa[0] = __float_as_uint(Pw[(g    ) * AT_PS + s8 + r    ]);
            pa[1] = __float_as_uint(Pw[(g + 8) * AT_PS + s8 + r    ]);
            pa[2] = __float_as_uint(Pw[(g    ) * AT_PS + s8 + r + 4]);
            pa[3] = __float_as_uint(Pw[(g + 8) * AT_PS + s8 + r + 4]);
            #pragma unroll
            for (int nt = 0; nt < 8; nt++) {
                uint32_t bfr[2];
                bfr[0] = __float_as_uint(Vs[(s8 + r    ) * AT_VS + nt * 8 + g]);
                bfr[1] = __float_as_uint(Vs[(s8 + r + 4) * AT_VS + nt * 8 + g]);
                mma8(oa[nt], pa, bfr);
            }
        }
    }

    float inv0 = 1.f / li0, inv1 = 1.f / li1;
    float* Ob = O + (size_t)b * T_ * C_ + h * 64;
    #pragma unroll
    for (int nt = 0; nt < 8; nt++) {
        int cc = nt * 8 + 2 * r;
        float2 o0 = make_float2(to_tf32(oa[nt][0] * inv0), to_tf32(oa[nt][1] * inv0));
        float2 o1 = make_float2(to_tf32(oa[nt][2] * inv1), to_tf32(oa[nt][3] * inv1));
        *(float2*)&Ob[(size_t)row0 * C_ + cc] = o0;
        *(float2*)&Ob[(size_t)row1 * C_ + cc] = o1;
    }
}

// ---------------- launcher -------------------------------------------------
extern "C" void kernel_launch(void* const* d_in, const int* in_sizes, int n_in,
                              void* d_out, int out_size) {
    const float* x     = (const float*)d_in[0];
    const float* Wq    = (const float*)d_in[1];
    const float* Wk    = (const float*)d_in[2];
    const float* Wv    = (const float*)d_in[3];
    const float* Wproj = (const float*)d_in[4];
    const float* bproj = (const float*)d_in[5];
    const float* W1    = (const float*)d_in[6];
    const float* b1    = (const float*)d_in[7];
    const float* W2    = (const float*)d_in[8];
    const float* b2    = (const float*)d_in[9];
    const float* ln1s  = (const float*)d_in[10];
    const float* ln1b  = (const float*)d_in[11];
    const float* ln2s  = (const float*)d_in[12];
    const float* ln2b  = (const float*)d_in[13];
    float* out = (float*)d_out;

    float *h, *wqkv, *wp, *w1, *w2, *qkv, *attn, *x1, *h2, *f1;
    cudaGetSymbolAddress((void**)&h,    g_h);
    cudaGetSymbolAddress((void**)&wqkv, g_wqkv);
    cudaGetSymbolAddress((void**)&wp,   g_wp);
    cudaGetSymbolAddress((void**)&w1,   g_w1);
    cudaGetSymbolAddress((void**)&w2,   g_w2);
    cudaGetSymbolAddress((void**)&qkv,  g_qkv);
    cudaGetSymbolAddress((void**)&attn, g_attn);
    cudaGetSymbolAddress((void**)&x1,   g_x1);
    cudaGetSymbolAddress((void**)&h2,   g_h2);
    cudaGetSymbolAddress((void**)&f1,   g_f1);

    cudaFuncSetAttribute(attn_mma,
                         cudaFuncAttributeMaxDynamicSharedMemorySize, ATT_SMEM_BYTES);
    cudaFuncSetAttribute(mma_gemm<0, 0>,
                         cudaFuncAttributeMaxDynamicSharedMemorySize, G_SMEM);
    cudaFuncSetAttribute(mma_gemm<0, 1>,
                         cudaFuncAttributeMaxDynamicSharedMemorySize, G_SMEM);
    cudaFuncSetAttribute(mma_gemm<1, 1>,
                         cudaFuncAttributeMaxDynamicSharedMemorySize, G_SMEM);

    // LN1 (rounded) + weight prep (rounded)
    ln_kernel<<<BT, 256>>>(x, ln1s, ln1b, h);
    pack_qkvw<<<C_ * C3 / 256, 256>>>(Wq, Wk, Wv, wqkv);
    round_copy<<<C_ * C_ / 1024, 256>>>(Wproj, wp);
    round_copy<<<C_ * FF / 1024, 256>>>(W1, w1);
    round_copy<<<FF * C_ / 1024, 256>>>(W2, w2);

    // fused QKV projection: [BT, C] @ [C, 3C] -> [BT, 3C]
    mma_gemm<0, 1><<<dim3(C3 / 128, BT / 128), 256, G_SMEM>>>(
        h, wqkv, nullptr, nullptr, qkv, BT, C3, C_);

    // attention
    attn_mma<<<dim3(T_ / 128, B_ * H_), 256, ATT_SMEM_BYTES>>>(qkv, attn);

    // out proj + residual
    dim3 g1(C_ / 128, BT / 128);
    mma_gemm<0, 0><<<g1, 256, G_SMEM>>>(attn, wp, bproj, x, x1, BT, C_, C_);

    // LN2 (rounded)
    ln_kernel<<<BT, 256>>>(x1, ln2s, ln2b, h2);

    // MLP
    mma_gemm<1, 1><<<dim3(FF / 128, BT / 128), 256, G_SMEM>>>(
        h2, w1, b1, nullptr, f1, BT, FF, C_);
    mma_gemm<0, 0><<<g1, 256, G_SMEM>>>(f1, w2, b2, x1, out, BT, C_, FF);
}

// round 7
// speedup vs baseline: 4.8979x; 1.4387x over previous
#include <cuda_runtime.h>
#include <cuda_fp16.h>
#include <cstdint>

// Problem constants
#define B_ 2
#define T_ 2048
#define C_ 1024
#define H_ 16
#define D_ 64
#define BT 4096          // B_*T_
#define FF 4096          // 4*C_
#define C3 3072          // 3*C_

// ---------------- scratch (static device globals) --------------------------
__device__ __half g_h   [BT * C_];   // LN1 output (fp16)
__device__ __half g_wqkv[C3 * C_];   // QKV weights [N=3C, K=C] fp16
__device__ __half g_wp  [C_ * C_];   // Wproj^T [N,K] fp16
__device__ __half g_w1  [FF * C_];   // W1^T [N=FF, K=C] fp16
__device__ __half g_w2  [C_ * FF];   // W2^T [N=C, K=FF] fp16
__device__ float  g_qkv [BT * C3];   // fused q|k|v [B,T,3C] fp32
__device__ __half g_attn[BT * C_];   // concat heads fp16
__device__ float  g_x1  [BT * C_];   // x + attn@Wproj + bproj (fp32)
__device__ __half g_h2  [BT * C_];   // LN2 output fp16
__device__ __half g_f1  [BT * FF];   // relu(h2@W1+b1) fp16

// helpers
__device__ __forceinline__ float to_tf32(float x) {
    uint32_t r;
    asm("cvt.rna.tf32.f32 %0, %1;" : "=r"(r) : "f"(x));
    return __uint_as_float(r);
}
__device__ __forceinline__ void mma8(float* c, const uint32_t* a, const uint32_t* b) {
    asm volatile(
        "mma.sync.aligned.m16n8k8.row.col.f32.tf32.tf32.f32 "
        "{%0,%1,%2,%3}, {%4,%5,%6,%7}, {%8,%9}, {%0,%1,%2,%3};"
        : "+f"(c[0]), "+f"(c[1]), "+f"(c[2]), "+f"(c[3])
        : "r"(a[0]), "r"(a[1]), "r"(a[2]), "r"(a[3]), "r"(b[0]), "r"(b[1]));
}
__device__ __forceinline__ void mma16(float* c, const uint32_t* a, const uint32_t* b) {
    asm volatile(
        "mma.sync.aligned.m16n8k16.row.col.f32.f16.f16.f32 "
        "{%0,%1,%2,%3}, {%4,%5,%6,%7}, {%8,%9}, {%0,%1,%2,%3};"
        : "+f"(c[0]), "+f"(c[1]), "+f"(c[2]), "+f"(c[3])
        : "r"(a[0]), "r"(a[1]), "r"(a[2]), "r"(a[3]), "r"(b[0]), "r"(b[1]));
}
__device__ __forceinline__ float2 exp2_f16x2(float t0, float t1) {
    __half2 hh = __floats2half2_rn(t0, t1);
    uint32_t hin = *reinterpret_cast<uint32_t*>(&hh);
    uint32_t hout;
    asm("ex2.approx.f16x2 %0, %1;" : "=r"(hout) : "r"(hin));
    __half2 he = *reinterpret_cast<__half2*>(&hout);
    return __half22float2(he);
}
__device__ __forceinline__ uint32_t smem_u32(const void* p) {
    uint32_t a;
    asm("{ .reg .u64 t; cvta.to.shared.u64 t, %1; cvt.u32.u64 %0, t; }"
        : "=r"(a) : "l"(p));
    return a;
}
#define CP16(dst, src) \
    asm volatile("cp.async.cg.shared.global [%0], [%1], 16;" \
                 :: "r"(dst), "l"(src) : "memory")
#define CP_COMMIT() asm volatile("cp.async.commit_group;" ::: "memory")
#define CP_WAIT1()  asm volatile("cp.async.wait_group 1;"  ::: "memory")

// ---------------- LayerNorm (fp32 in, fp16 out) ---------------------------
__global__ void ln_kernel(const float* __restrict__ x,
                          const float* __restrict__ sc,
                          const float* __restrict__ bi,
                          __half* __restrict__ out) {
    int row = blockIdx.x;
    const float* xr = x + (size_t)row * C_;
    __half* orow = out + (size_t)row * C_;
    int tid = threadIdx.x;

    float4 v = ((const float4*)xr)[tid];
    float s  = v.x + v.y + v.z + v.w;
    float ss = v.x*v.x + v.y*v.y + v.z*v.z + v.w*v.w;
    #pragma unroll
    for (int o = 16; o; o >>= 1) {
        s  += __shfl_xor_sync(0xffffffffu, s,  o);
        ss += __shfl_xor_sync(0xffffffffu, ss, o);
    }
    __shared__ float sm[8], sm2[8];
    if ((tid & 31) == 0) { sm[tid >> 5] = s; sm2[tid >> 5] = ss; }
    __syncthreads();
    if (tid < 32) {
        float a  = (tid < 8) ? sm[tid]  : 0.f;
        float b2 = (tid < 8) ? sm2[tid] : 0.f;
        #pragma unroll
        for (int o = 4; o; o >>= 1) {
            a  += __shfl_xor_sync(0xffffffffu, a,  o);
            b2 += __shfl_xor_sync(0xffffffffu, b2, o);
        }
        if (tid == 0) { sm[0] = a; sm2[0] = b2; }
    }
    __syncthreads();
    float mean = sm[0] * (1.f / C_);
    float var  = sm2[0] * (1.f / C_) - mean * mean;
    float rstd = rsqrtf(var + 1e-6f);

    float4 sv = ((const float4*)sc)[tid];
    float4 bv = ((const float4*)bi)[tid];
    __half2 h0 = __floats2half2_rn((v.x - mean) * rstd * sv.x + bv.x,
                                   (v.y - mean) * rstd * sv.y + bv.y);
    __half2 h1 = __floats2half2_rn((v.z - mean) * rstd * sv.z + bv.z,
                                   (v.w - mean) * rstd * sv.w + bv.w);
    uint2 o8;
    o8.x = *reinterpret_cast<uint32_t*>(&h0);
    o8.y = *reinterpret_cast<uint32_t*>(&h1);
    *(uint2*)&orow[tid * 4] = o8;
}

// ---------------- transpose fp32 [R,Cc] -> fp16 [Cc,R], batched ------------
__global__ void transp_h(const float* __restrict__ src, __half* __restrict__ dst,
                         int R, int Cc, long sstride, long dstride) {
    __shared__ float t[32][33];
    src += (long)blockIdx.z * sstride;
    dst += (long)blockIdx.z * dstride;
    int r0 = blockIdx.y * 32, c0 = blockIdx.x * 32;
    int x = threadIdx.x, y = threadIdx.y;
    #pragma unroll
    for (int i = 0; i < 32; i += 8)
        t[y + i][x] = src[(size_t)(r0 + y + i) * Cc + c0 + x];
    __syncthreads();
    #pragma unroll
    for (int i = 0; i < 32; i += 8)
        dst[(size_t)(c0 + y + i) * R + r0 + x] = __float2half(t[x][y + i]);
}

// ---------------- fp16 mma.sync GEMM (m16n8k16, cp.async 3-stage) ----------
// C[M,N] = A[M,K] @ Bw[N,K]^T (+bias)(+resid)(relu). A,Bw fp16; C fp32 or fp16.
// CTA 128x128, BK=32. SMEM per stage: A 128x40h + B 128x40h = 20480 B.
#define H_SA 40                       // halves stride (80 B, 16B-aligned)
#define H_STG_H (128 * H_SA * 2)      // halves per stage (A + B)
#define H_BOFF  (128 * H_SA)          // B offset (halves)
#define H_STG_BY (H_STG_H * 2)        // 20480 bytes
#define H_SMEM  (3 * H_STG_BY)        // 61440 bytes

template <int RELU, int HOUT>
__global__ void __launch_bounds__(256, 2) hgemm(
    const __half* __restrict__ A, const __half* __restrict__ Bw,
    const float* __restrict__ bias, const float* __restrict__ resid,
    void* __restrict__ Cout, int M, int N, int K)
{
    extern __shared__ __half smh[];
    uint32_t sbase = smem_u32(smh);

    int tid  = threadIdx.x;
    int wid  = tid >> 5, lane = tid & 31;
    int g    = lane >> 2, r = lane & 3;
    int bm   = blockIdx.y, bn = blockIdx.x;
    int wm   = (wid & 1) * 64;
    int wn   = (wid >> 1) * 32;

    const __half* Ab = A  + (size_t)bm * 128 * K;
    const __half* Bb = Bw + (size_t)bn * 128 * K;

    int lr = tid >> 2, seg = tid & 3;           // row 0..63, 16B segment
    const __half* Asrc = Ab + (size_t)lr * K + seg * 8;
    const __half* Bsrc = Bb + (size_t)lr * K + seg * 8;
    uint32_t ad0 = sbase + (uint32_t)(lr * 80 + seg * 16);
    uint32_t ad1 = ad0 + 64 * 80;
    uint32_t bd0 = sbase + (uint32_t)(H_BOFF * 2 + lr * 80 + seg * 16);
    uint32_t bd1 = bd0 + 64 * 80;
    const size_t a64 = (size_t)64 * K;

    float c[4][4][4];
    #pragma unroll
    for (int mt = 0; mt < 4; mt++)
        #pragma unroll
        for (int nt = 0; nt < 4; nt++)
            #pragma unroll
            for (int i = 0; i < 4; i++) c[mt][nt][i] = 0.f;

    int nch = K >> 5;

    // prologue: stages 0,1
    CP16(ad0, Asrc);        CP16(ad1, Asrc + a64);
    CP16(bd0, Bsrc);        CP16(bd1, Bsrc + a64);
    CP_COMMIT();
    CP16(ad0 + H_STG_BY, Asrc + 32);        CP16(ad1 + H_STG_BY, Asrc + a64 + 32);
    CP16(bd0 + H_STG_BY, Bsrc + 32);        CP16(bd1 + H_STG_BY, Bsrc + a64 + 32);
    CP_COMMIT();

    for (int ch = 0; ch < nch; ch++) {
        int st = ch % 3;
        CP_WAIT1();
        __syncthreads();

        const __half* Ap = smh + st * H_STG_H;
        const __half* Bp = Ap + H_BOFF;
        #pragma unroll
        for (int ks = 0; ks < 2; ks++) {
            int kk = ks * 16;
            uint32_t af[4][4], bf[4][2];
            #pragma unroll
            for (int mt = 0; mt < 4; mt++) {
                int m = wm + mt * 16 + g;
                af[mt][0] = *(const uint32_t*)&Ap[(m    ) * H_SA + kk + 2 * r    ];
                af[mt][1] = *(const uint32_t*)&Ap[(m + 8) * H_SA + kk + 2 * r    ];
                af[mt][2] = *(const uint32_t*)&Ap[(m    ) * H_SA + kk + 2 * r + 8];
                af[mt][3] = *(const uint32_t*)&Ap[(m + 8) * H_SA + kk + 2 * r + 8];
            }
            #pragma unroll
            for (int nt = 0; nt < 4; nt++) {
                int n = wn + nt * 8 + g;
                bf[nt][0] = *(const uint32_t*)&Bp[n * H_SA + kk + 2 * r    ];
                bf[nt][1] = *(const uint32_t*)&Bp[n * H_SA + kk + 2 * r + 8];
            }
            #pragma unroll
            for (int mt = 0; mt < 4; mt++)
                #pragma unroll
                for (int nt = 0; nt < 4; nt++)
                    mma16(c[mt][nt], af[mt], bf[nt]);
        }

        int nc2 = ch + 2;
        if (nc2 < nch) {
            int kt = nc2 << 5;
            uint32_t so = (uint32_t)(nc2 % 3) * H_STG_BY;
            CP16(ad0 + so, Asrc + kt);  CP16(ad1 + so, Asrc + a64 + kt);
            CP16(bd0 + so, Bsrc + kt);  CP16(bd1 + so, Bsrc + a64 + kt);
        }
        CP_COMMIT();
    }

    // epilogue
    #pragma unroll
    for (int mt = 0; mt < 4; mt++) {
        #pragma unroll
        for (int rr = 0; rr < 2; rr++) {
            int m = bm * 128 + wm + mt * 16 + g + rr * 8;
            const float* Rrow = resid ? resid + (size_t)m * N + bn * 128 : nullptr;
            #pragma unroll
            for (int nt = 0; nt < 4; nt++) {
                int nc = wn + nt * 8 + 2 * r;
                float v0 = c[mt][nt][rr * 2 + 0];
                float v1 = c[mt][nt][rr * 2 + 1];
                if (bias)  { v0 += bias[bn * 128 + nc]; v1 += bias[bn * 128 + nc + 1]; }
                if (resid) { v0 += Rrow[nc]; v1 += Rrow[nc + 1]; }
                if (RELU)  { v0 = fmaxf(v0, 0.f); v1 = fmaxf(v1, 0.f); }
                if (HOUT) {
                    __half* Crow = (__half*)Cout + (size_t)m * N + bn * 128;
                    *(__half2*)&Crow[nc] = __floats2half2_rn(v0, v1);
                } else {
                    float* Crow = (float*)Cout + (size_t)m * N + bn * 128;
                    *(float2*)&Crow[nc] = make_float2(v0, v1);
                }
            }
        }
    }
}

// ---------------- tensor-core flash attention (tf32, fp32 in, fp16 out) ----
#define AT_KS 68
#define AT_VS 72
#define AT_PS 68
#define ATT_SMEM_BYTES ((64*AT_KS + 64*AT_VS + 128*AT_PS) * 4)
#define LOG2E 1.4426950408889634f

__global__ void __launch_bounds__(256, 1) attn_mma(
    const float* __restrict__ QKV, __half* __restrict__ O)
{
    extern __shared__ float smf[];
    float* Ks = smf;
    float* Vs = Ks + 64 * AT_KS;
    float* Ps = Vs + 64 * AT_VS;

    int tid = threadIdx.x;
    int wid = tid >> 5, lane = tid & 31;
    int g = lane >> 2, r = lane & 3;
    int b = blockIdx.y >> 4, h = blockIdx.y & 15;
    int q0 = blockIdx.x * 128;
    int m0 = wid * 16;

    const float* Qb = QKV + (size_t)b * T_ * C3 + h * 64;
    const float* Kb = Qb + C_;
    const float* Vb = Qb + 2 * C_;

    int row0 = q0 + m0 + g;
    int row1 = row0 + 8;

    uint32_t qa[8][4];
    #pragma unroll
    for (int kk = 0; kk < 8; kk++) {
        int d0 = kk * 8;
        qa[kk][0] = __float_as_uint(to_tf32(Qb[(size_t)row0 * C3 + d0 + r    ]));
        qa[kk][1] = __float_as_uint(to_tf32(Qb[(size_t)row1 * C3 + d0 + r    ]));
        qa[kk][2] = __float_as_uint(to_tf32(Qb[(size_t)row0 * C3 + d0 + r + 4]));
        qa[kk][3] = __float_as_uint(to_tf32(Qb[(size_t)row1 * C3 + d0 + r + 4]));
    }

    float oa[8][4];
    #pragma unroll
    for (int nt = 0; nt < 8; nt++)
        #pragma unroll
        for (int i = 0; i < 4; i++) oa[nt][i] = 0.f;
    float mi0 = -1e30f, mi1 = -1e30f, li0 = 0.f, li1 = 0.f;

    float* Pw = Ps + m0 * AT_PS;

    int ntiles = (q0 >> 6) + 2;
    for (int kt = 0; kt < ntiles; kt++) {
        int k0 = kt << 6;
        __syncthreads();
        for (int i = tid; i < 64 * 16; i += 256) {
            int rr = i >> 4, d4 = (i & 15) << 2;
            float4 kv = *(const float4*)(Kb + (size_t)(k0 + rr) * C3 + d4);
            kv.x = to_tf32(kv.x); kv.y = to_tf32(kv.y);
            kv.z = to_tf32(kv.z); kv.w = to_tf32(kv.w);
            *(float4*)&Ks[rr * AT_KS + d4] = kv;
            float4 vv = *(const float4*)(Vb + (size_t)(k0 + rr) * C3 + d4);
            vv.x = to_tf32(vv.x); vv.y = to_tf32(vv.y);
            vv.z = to_tf32(vv.z); vv.w = to_tf32(vv.w);
            *(float4*)&Vs[rr * AT_VS + d4] = vv;
        }
        __syncthreads();

        float sc[8][4];
        #pragma unroll
        for (int nt = 0; nt < 8; nt++)
            #pragma unroll
            for (int i = 0; i < 4; i++) sc[nt][i] = 0.f;
        #pragma unroll
        for (int kk = 0; kk < 8; kk++) {
            int d0 = kk * 8;
            #pragma unroll
            for (int nt = 0; nt < 8; nt++) {
                uint32_t bfr[2];
                bfr[0] = __float_as_uint(Ks[(nt * 8 + g) * AT_KS + d0 + r    ]);
                bfr[1] = __float_as_uint(Ks[(nt * 8 + g) * AT_KS + d0 + r + 4]);
                mma8(sc[nt], qa[kk], bfr);
            }
        }

        float mx0 = -1e30f, mx1 = -1e30f;
        #pragma unroll
        for (int nt = 0; nt < 8; nt++) {
            int c0 = k0 + nt * 8 + 2 * r;
            int c1 = c0 + 1;
            sc[nt][0] = (c0 <= row0) ? sc[nt][0] * 0.03125f : -1e30f;
            sc[nt][1] = (c1 <= row0) ? sc[nt][1] * 0.03125f : -1e30f;
            sc[nt][2] = (c0 <= row1) ? sc[nt][2] * 0.03125f : -1e30f;
            sc[nt][3] = (c1 <= row1) ? sc[nt][3] * 0.03125f : -1e30f;
            mx0 = fmaxf(mx0, fmaxf(sc[nt][0], sc[nt][1]));
            mx1 = fmaxf(mx1, fmaxf(sc[nt][2], sc[nt][3]));
        }
        mx0 = fmaxf(mx0, __shfl_xor_sync(0xffffffffu, mx0, 1));
        mx0 = fmaxf(mx0, __shfl_xor_sync(0xffffffffu, mx0, 2));
        mx1 = fmaxf(mx1, __shfl_xor_sync(0xffffffffu, mx1, 1));
        mx1 = fmaxf(mx1, __shfl_xor_sync(0xffffffffu, mx1, 2));

        float mn0 = fmaxf(mi0, mx0), mn1 = fmaxf(mi1, mx1);
        float corr0 = __expf(mi0 - mn0);
        float corr1 = __expf(mi1 - mn1);

        float s0 = 0.f, s1 = 0.f;
        #pragma unroll
        for (int nt = 0; nt < 8; nt++) {
            float2 p01 = exp2_f16x2((sc[nt][0] - mn0) * LOG2E,
                                    (sc[nt][1] - mn0) * LOG2E);
            float2 p23 = exp2_f16x2((sc[nt][2] - mn1) * LOG2E,
                                    (sc[nt][3] - mn1) * LOG2E);
            p01.x = to_tf32(p01.x); p01.y = to_tf32(p01.y);
            p23.x = to_tf32(p23.x); p23.y = to_tf32(p23.y);
            s0 += p01.x + p01.y;
            s1 += p23.x + p23.y;
            *(float2*)&Pw[(g    ) * AT_PS + nt * 8 + 2 * r] = p01;
            *(float2*)&Pw[(g + 8) * AT_PS + nt * 8 + 2 * r] = p23;
        }
        s0 += __shfl_xor_sync(0xffffffffu, s0, 1);
        s0 += __shfl_xor_sync(0xffffffffu, s0, 2);
        s1 += __shfl_xor_sync(0xffffffffu, s1, 1);
        s1 += __shfl_xor_sync(0xffffffffu, s1, 2);
        li0 = li0 * corr0 + s0;
        li1 = li1 * corr1 + s1;
        mi0 = mn0; mi1 = mn1;

        #pragma unroll
        for (int nt = 0; nt < 8; nt++) {
            oa[nt][0] *= corr0; oa[nt][1] *= corr0;
            oa[nt][2] *= corr1; oa[nt][3] *= corr1;
        }
        __syncwarp();

        #pragma unroll
        for (int kk = 0; kk < 8; kk++) {
            int s8 = kk * 8;
            uint32_t pa[4];
            pa[0] = __float_as_uint(Pw[(g    ) * AT_PS + s8 + r    ]);
            pa[1] = __float_as_uint(Pw[(g + 8) * AT_PS + s8 + r    ]);
            pa[2] = __float_as_uint(Pw[(g    ) * AT_PS + s8 + r + 4]);
            pa[3] = __float_as_uint(Pw[(g + 8) * AT_PS + s8 + r + 4]);
            #pragma unroll
            for (int nt = 0; nt < 8; nt++) {
                uint32_t bfr[2];
                bfr[0] = __float_as_uint(Vs[(s8 + r    ) * AT_VS + nt * 8 + g]);
                bfr[1] = __float_as_uint(Vs[(s8 + r + 4) * AT_VS + nt * 8 + g]);
                mma8(oa[nt], pa, bfr);
            }
        }
    }

    float inv0 = 1.f / li0, inv1 = 1.f / li1;
    __half* Ob = O + (size_t)b * T_ * C_ + h * 64;
    #pragma unroll
    for (int nt = 0; nt < 8; nt++) {
        int cc = nt * 8 + 2 * r;
        *(__half2*)&Ob[(size_t)row0 * C_ + cc] =
            __floats2half2_rn(oa[nt][0] * inv0, oa[nt][1] * inv0);
        *(__half2*)&Ob[(size_t)row1 * C_ + cc] =
            __floats2half2_rn(oa[nt][2] * inv1, oa[nt][3] * inv1);
    }
}

// ---------------- launcher -------------------------------------------------
extern "C" void kernel_launch(void* const* d_in, const int* in_sizes, int n_in,
                              void* d_out, int out_size) {
    const float* x     = (const float*)d_in[0];
    const float* Wq    = (const float*)d_in[1];
    const float* Wk    = (const float*)d_in[2];
    const float* Wv    = (const float*)d_in[3];
    const float* Wproj = (const float*)d_in[4];
    const float* bproj = (const float*)d_in[5];
    const float* W1    = (const float*)d_in[6];
    const float* b1    = (const float*)d_in[7];
    const float* W2    = (const float*)d_in[8];
    const float* b2    = (const float*)d_in[9];
    const float* ln1s  = (const float*)d_in[10];
    const float* ln1b  = (const float*)d_in[11];
    const float* ln2s  = (const float*)d_in[12];
    const float* ln2b  = (const float*)d_in[13];
    float* out = (float*)d_out;

    __half *h, *wqkv, *wp, *w1, *w2, *attn, *h2, *f1;
    float *qkv, *x1;
    cudaGetSymbolAddress((void**)&h,    g_h);
    cudaGetSymbolAddress((void**)&wqkv, g_wqkv);
    cudaGetSymbolAddress((void**)&wp,   g_wp);
    cudaGetSymbolAddress((void**)&w1,   g_w1);
    cudaGetSymbolAddress((void**)&w2,   g_w2);
    cudaGetSymbolAddress((void**)&qkv,  g_qkv);
    cudaGetSymbolAddress((void**)&attn, g_attn);
    cudaGetSymbolAddress((void**)&x1,   g_x1);
    cudaGetSymbolAddress((void**)&h2,   g_h2);
    cudaGetSymbolAddress((void**)&f1,   g_f1);

    cudaFuncSetAttribute(attn_mma,
                         cudaFuncAttributeMaxDynamicSharedMemorySize, ATT_SMEM_BYTES);
    cudaFuncSetAttribute(hgemm<0, 0>,
                         cudaFuncAttributeMaxDynamicSharedMemorySize, H_SMEM);
    cudaFuncSetAttribute(hgemm<1, 1>,
                         cudaFuncAttributeMaxDynamicSharedMemorySize, H_SMEM);

    dim3 tb(32, 8);

    // LN1 (fp16 out) + weight transposes to [N,K] fp16
    ln_kernel<<<BT, 256>>>(x, ln1s, ln1b, h);
    transp_h<<<dim3(2, 32, 16), tb>>>(Wq, wqkv,             C_, 64, (long)C_ * 64, (long)64 * C_);
    transp_h<<<dim3(2, 32, 16), tb>>>(Wk, wqkv + C_ * C_,   C_, 64, (long)C_ * 64, (long)64 * C_);
    transp_h<<<dim3(2, 32, 16), tb>>>(Wv, wqkv + 2 * C_ * C_, C_, 64, (long)C_ * 64, (long)64 * C_);
    transp_h<<<dim3(32, 32, 1),  tb>>>(Wproj, wp, C_, C_, 0, 0);
    transp_h<<<dim3(128, 32, 1), tb>>>(W1, w1, C_, FF, 0, 0);
    transp_h<<<dim3(32, 128, 1), tb>>>(W2, w2, FF, C_, 0, 0);

    // fused QKV projection: [BT,C] fp16 @ [3C,C]^T -> [BT,3C] fp32
    hgemm<0, 0><<<dim3(C3 / 128, BT / 128), 256, H_SMEM>>>(
        h, wqkv, nullptr, nullptr, qkv, BT, C3, C_);

    // attention (tf32, fp16 output)
    attn_mma<<<dim3(T_ / 128, B_ * H_), 256, ATT_SMEM_BYTES>>>(qkv, attn);

    // out proj + residual (fp32 out)
    dim3 g1(C_ / 128, BT / 128);
    hgemm<0, 0><<<g1, 256, H_SMEM>>>(attn, wp, bproj, x, x1, BT, C_, C_);

    // LN2 (fp16 out)
    ln_kernel<<<BT, 256>>>(x1, ln2s, ln2b, h2);

    // MLP
    hgemm<1, 1><<<dim3(FF / 128, BT / 128), 256, H_SMEM>>>(
        h2, w1, b1, nullptr, f1, BT, FF, C_);
    hgemm<0, 0><<<g1, 256, H_SMEM>>>(f1, w2, b2, x1, out, BT, C_, FF);
}

// round 8
// speedup vs baseline: 6.6255x; 1.3527x over previous
#include <cuda_runtime.h>
#include <cuda_fp16.h>
#include <cstdint>

// Problem constants
#define B_ 2
#define T_ 2048
#define C_ 1024
#define H_ 16
#define D_ 64
#define BT 4096          // B_*T_
#define FF 4096          // 4*C_
#define C3 3072          // 3*C_

// ---------------- scratch (static device globals) --------------------------
__device__ __half g_h   [BT * C_];   // LN1 output (fp16)
__device__ __half g_wqkv[C3 * C_];   // QKV weights [N=3C, K=C] fp16
__device__ __half g_wp  [C_ * C_];   // Wproj^T [N,K] fp16
__device__ __half g_w1  [FF * C_];   // W1^T [N=FF, K=C] fp16
__device__ __half g_w2  [C_ * FF];   // W2^T [N=C, K=FF] fp16
__device__ __half g_qkv [BT * C3];   // fused q|k|v [B,T,3C] fp16
__device__ __half g_attn[BT * C_];   // concat heads fp16
__device__ float  g_x1  [BT * C_];   // x + attn@Wproj + bproj (fp32)
__device__ __half g_h2  [BT * C_];   // LN2 output fp16
__device__ __half g_f1  [BT * FF];   // relu(h2@W1+b1) fp16

// ---------------- helpers --------------------------------------------------
__device__ __forceinline__ void mma16(float* c, const uint32_t* a, const uint32_t* b) {
    asm volatile(
        "mma.sync.aligned.m16n8k16.row.col.f32.f16.f16.f32 "
        "{%0,%1,%2,%3}, {%4,%5,%6,%7}, {%8,%9}, {%0,%1,%2,%3};"
        : "+f"(c[0]), "+f"(c[1]), "+f"(c[2]), "+f"(c[3])
        : "r"(a[0]), "r"(a[1]), "r"(a[2]), "r"(a[3]), "r"(b[0]), "r"(b[1]));
}
#define LDSM4(R0, R1, R2, R3, addr) \
    asm volatile("ldmatrix.sync.aligned.m8n8.x4.shared.b16 {%0,%1,%2,%3}, [%4];" \
                 : "=r"(R0), "=r"(R1), "=r"(R2), "=r"(R3) : "r"(addr))
#define LDSM4T(R0, R1, R2, R3, addr) \
    asm volatile("ldmatrix.sync.aligned.m8n8.x4.trans.shared.b16 {%0,%1,%2,%3}, [%4];" \
                 : "=r"(R0), "=r"(R1), "=r"(R2), "=r"(R3) : "r"(addr))

// packed half2 exp2: returns raw half2 bits, also float2
__device__ __forceinline__ uint32_t exp2h2(float t0, float t1, float2* f) {
    __half2 hh = __floats2half2_rn(t0, t1);
    uint32_t hin = *reinterpret_cast<uint32_t*>(&hh);
    uint32_t hout;
    asm("ex2.approx.f16x2 %0, %1;" : "=r"(hout) : "r"(hin));
    __half2 he = *reinterpret_cast<__half2*>(&hout);
    *f = __half22float2(he);
    return hout;
}
__device__ __forceinline__ uint32_t smem_u32(const void* p) {
    uint32_t a;
    asm("{ .reg .u64 t; cvta.to.shared.u64 t, %1; cvt.u32.u64 %0, t; }"
        : "=r"(a) : "l"(p));
    return a;
}
#define CP16(dst, src) \
    asm volatile("cp.async.cg.shared.global [%0], [%1], 16;" \
                 :: "r"(dst), "l"(src) : "memory")
#define CP_COMMIT() asm volatile("cp.async.commit_group;" ::: "memory")
#define CP_WAIT1()  asm volatile("cp.async.wait_group 1;"  ::: "memory")

// ---------------- LayerNorm (fp32 in, fp16 out) ---------------------------
__global__ void ln_kernel(const float* __restrict__ x,
                          const float* __restrict__ sc,
                          const float* __restrict__ bi,
                          __half* __restrict__ out) {
    int row = blockIdx.x;
    const float* xr = x + (size_t)row * C_;
    __half* orow = out + (size_t)row * C_;
    int tid = threadIdx.x;

    float4 v = ((const float4*)xr)[tid];
    float s  = v.x + v.y + v.z + v.w;
    float ss = v.x*v.x + v.y*v.y + v.z*v.z + v.w*v.w;
    #pragma unroll
    for (int o = 16; o; o >>= 1) {
        s  += __shfl_xor_sync(0xffffffffu, s,  o);
        ss += __shfl_xor_sync(0xffffffffu, ss, o);
    }
    __shared__ float sm[8], sm2[8];
    if ((tid & 31) == 0) { sm[tid >> 5] = s; sm2[tid >> 5] = ss; }
    __syncthreads();
    if (tid < 32) {
        float a  = (tid < 8) ? sm[tid]  : 0.f;
        float b2 = (tid < 8) ? sm2[tid] : 0.f;
        #pragma unroll
        for (int o = 4; o; o >>= 1) {
            a  += __shfl_xor_sync(0xffffffffu, a,  o);
            b2 += __shfl_xor_sync(0xffffffffu, b2, o);
        }
        if (tid == 0) { sm[0] = a; sm2[0] = b2; }
    }
    __syncthreads();
    float mean = sm[0] * (1.f / C_);
    float var  = sm2[0] * (1.f / C_) - mean * mean;
    float rstd = rsqrtf(var + 1e-6f);

    float4 sv = ((const float4*)sc)[tid];
    float4 bv = ((const float4*)bi)[tid];
    __half2 h0 = __floats2half2_rn((v.x - mean) * rstd * sv.x + bv.x,
                                   (v.y - mean) * rstd * sv.y + bv.y);
    __half2 h1 = __floats2half2_rn((v.z - mean) * rstd * sv.z + bv.z,
                                   (v.w - mean) * rstd * sv.w + bv.w);
    uint2 o8;
    o8.x = *reinterpret_cast<uint32_t*>(&h0);
    o8.y = *reinterpret_cast<uint32_t*>(&h1);
    *(uint2*)&orow[tid * 4] = o8;
}

// ---------------- transpose fp32 [R,Cc] -> fp16 [Cc,R], batched ------------
__global__ void transp_h(const float* __restrict__ src, __half* __restrict__ dst,
                         int R, int Cc, long sstride, long dstride) {
    __shared__ float t[32][33];
    src += (long)blockIdx.z * sstride;
    dst += (long)blockIdx.z * dstride;
    int r0 = blockIdx.y * 32, c0 = blockIdx.x * 32;
    int x = threadIdx.x, y = threadIdx.y;
    #pragma unroll
    for (int i = 0; i < 32; i += 8)
        t[y + i][x] = src[(size_t)(r0 + y + i) * Cc + c0 + x];
    __syncthreads();
    #pragma unroll
    for (int i = 0; i < 32; i += 8)
        dst[(size_t)(c0 + y + i) * R + r0 + x] = __float2half(t[x][y + i]);
}

// ---------------- fp16 GEMM (m16n8k16 + ldmatrix + cp.async 3-stage) -------
// C[M,N] = A[M,K] @ Bw[N,K]^T (+bias)(+resid)(relu). fp16 in; fp32/fp16 out.
#define H_SA 40                       // halves stride (80 B)
#define H_STG_H (128 * H_SA * 2)
#define H_BOFF  (128 * H_SA)
#define H_STG_BY (H_STG_H * 2)        // 20480 bytes
#define H_SMEM  (3 * H_STG_BY)        // 61440 bytes

template <int RELU, int HOUT>
__global__ void __launch_bounds__(256, 2) hgemm(
    const __half* __restrict__ A, const __half* __restrict__ Bw,
    const float* __restrict__ bias, const float* __restrict__ resid,
    void* __restrict__ Cout, int M, int N, int K)
{
    extern __shared__ __half smh[];
    uint32_t sbase = smem_u32(smh);

    int tid  = threadIdx.x;
    int wid  = tid >> 5, lane = tid & 31;
    int g    = lane >> 2, r = lane & 3;
    int bm   = blockIdx.y, bn = blockIdx.x;
    int wm   = (wid & 1) * 64;
    int wn   = (wid >> 1) * 32;

    const __half* Ab = A  + (size_t)bm * 128 * K;
    const __half* Bb = Bw + (size_t)bn * 128 * K;

    int lr = tid >> 2, seg = tid & 3;
    const __half* Asrc = Ab + (size_t)lr * K + seg * 8;
    const __half* Bsrc = Bb + (size_t)lr * K + seg * 8;
    uint32_t ad0 = sbase + (uint32_t)(lr * 80 + seg * 16);
    uint32_t ad1 = ad0 + 64 * 80;
    uint32_t bd0 = sbase + (uint32_t)(H_BOFF * 2 + lr * 80 + seg * 16);
    uint32_t bd1 = bd0 + 64 * 80;
    const size_t a64 = (size_t)64 * K;

    // ldmatrix per-thread offsets (bytes)
    // A-type: row += (mi&1)*8, col += (mi>>1)*8
    uint32_t aoff = (uint32_t)(((lane & 7) + ((lane >> 3) & 1) * 8) * H_SA
                               + (lane >> 4) * 8) * 2;
    // B-type: row += (mi>>1)*8, col += (mi&1)*8
    uint32_t boff = (uint32_t)(((lane & 7) + ((lane >> 4) & 1) * 8) * H_SA
                               + ((lane >> 3) & 1) * 8) * 2;

    float c[4][4][4];
    #pragma unroll
    for (int mt = 0; mt < 4; mt++)
        #pragma unroll
        for (int nt = 0; nt < 4; nt++)
            #pragma unroll
            for (int i = 0; i < 4; i++) c[mt][nt][i] = 0.f;

    int nch = K >> 5;

    CP16(ad0, Asrc);        CP16(ad1, Asrc + a64);
    CP16(bd0, Bsrc);        CP16(bd1, Bsrc + a64);
    CP_COMMIT();
    CP16(ad0 + H_STG_BY, Asrc + 32);  CP16(ad1 + H_STG_BY, Asrc + a64 + 32);
    CP16(bd0 + H_STG_BY, Bsrc + 32);  CP16(bd1 + H_STG_BY, Bsrc + a64 + 32);
    CP_COMMIT();

    for (int ch = 0; ch < nch; ch++) {
        int st = ch % 3;
        CP_WAIT1();
        __syncthreads();

        uint32_t abase = sbase + (uint32_t)st * H_STG_BY + aoff;
        uint32_t bbase = sbase + (uint32_t)st * H_STG_BY + H_BOFF * 2 + boff;
        #pragma unroll
        for (int ks = 0; ks < 2; ks++) {
            int kk = ks * 16;
            uint32_t af[4][4], bf[4][2];
            #pragma unroll
            for (int mt = 0; mt < 4; mt++)
                LDSM4(af[mt][0], af[mt][1], af[mt][2], af[mt][3],
                      abase + (uint32_t)(((wm + mt * 16) * H_SA + kk) * 2));
            #pragma unroll
            for (int np = 0; np < 2; np++) {
                uint32_t r0, r1, r2, r3;
                LDSM4(r0, r1, r2, r3,
                      bbase + (uint32_t)(((wn + np * 16) * H_SA + kk) * 2));
                bf[2 * np][0] = r0; bf[2 * np][1] = r1;
                bf[2 * np + 1][0] = r2; bf[2 * np + 1][1] = r3;
            }
            #pragma unroll
            for (int mt = 0; mt < 4; mt++)
                #pragma unroll
                for (int nt = 0; nt < 4; nt++)
                    mma16(c[mt][nt], af[mt], bf[nt]);
        }

        int nc2 = ch + 2;
        if (nc2 < nch) {
            int kt = nc2 << 5;
            uint32_t so = (uint32_t)(nc2 % 3) * H_STG_BY;
            CP16(ad0 + so, Asrc + kt);  CP16(ad1 + so, Asrc + a64 + kt);
            CP16(bd0 + so, Bsrc + kt);  CP16(bd1 + so, Bsrc + a64 + kt);
        }
        CP_COMMIT();
    }

    #pragma unroll
    for (int mt = 0; mt < 4; mt++) {
        #pragma unroll
        for (int rr = 0; rr < 2; rr++) {
            int m = bm * 128 + wm + mt * 16 + g + rr * 8;
            const float* Rrow = resid ? resid + (size_t)m * N + bn * 128 : nullptr;
            #pragma unroll
            for (int nt = 0; nt < 4; nt++) {
                int nc = wn + nt * 8 + 2 * r;
                float v0 = c[mt][nt][rr * 2 + 0];
                float v1 = c[mt][nt][rr * 2 + 1];
                if (bias)  { v0 += bias[bn * 128 + nc]; v1 += bias[bn * 128 + nc + 1]; }
                if (resid) { v0 += Rrow[nc]; v1 += Rrow[nc + 1]; }
                if (RELU)  { v0 = fmaxf(v0, 0.f); v1 = fmaxf(v1, 0.f); }
                if (HOUT) {
                    __half* Crow = (__half*)Cout + (size_t)m * N + bn * 128;
                    *(__half2*)&Crow[nc] = __floats2half2_rn(v0, v1);
                } else {
                    float* Crow = (float*)Cout + (size_t)m * N + bn * 128;
                    *(float2*)&Crow[nc] = make_float2(v0, v1);
                }
            }
        }
    }
}

// ---------------- fp16 tensor-core flash attention -------------------------
// QKV fp16 [BT, 3C]. 128 q-rows/CTA (8 warps x 16), 64-key tiles.
// K frags: ldmatrix.x4; V frags: ldmatrix.x4.trans (no smem transpose);
// P: raw f16x2-exp bits, reloaded via ldmatrix.x4.
#define AT_S 72                                  // halves stride
#define ATT_SMEM_BYTES ((64 * AT_S + 64 * AT_S + 128 * AT_S) * 2)   // 36864
#define LOG2E 1.4426950408889634f

__global__ void __launch_bounds__(256, 1) attn_h(
    const __half* __restrict__ QKV, __half* __restrict__ O)
{
    extern __shared__ __half sma[];
    __half* Ks = sma;
    __half* Vs = Ks + 64 * AT_S;
    __half* Ps = Vs + 64 * AT_S;
    uint32_t ks_b = smem_u32(Ks);
    uint32_t vs_b = smem_u32(Vs);

    int tid = threadIdx.x;
    int wid = tid >> 5, lane = tid & 31;
    int g = lane >> 2, r = lane & 3;
    int b = blockIdx.y >> 4, h = blockIdx.y & 15;
    int q0 = blockIdx.x * 128;
    int m0 = wid * 16;

    const __half* Qb = QKV + (size_t)b * T_ * C3 + h * 64;
    const __half* Kb = Qb + C_;
    const __half* Vb = Qb + 2 * C_;

    int row0 = q0 + m0 + g;
    int row1 = row0 + 8;

    // ldmatrix per-thread offsets (bytes)
    uint32_t kb_off = (uint32_t)(((lane & 7) + ((lane >> 4) & 1) * 8) * AT_S
                                 + ((lane >> 3) & 1) * 8) * 2;   // B-type (Ks)
    uint32_t vb_off = (uint32_t)(((lane & 7) + ((lane >> 3) & 1) * 8) * AT_S
                                 + (lane >> 4) * 8) * 2;          // trans (Vs)
    uint32_t pa_off = (uint32_t)(((lane & 7) + ((lane >> 3) & 1) * 8) * AT_S
                                 + (lane >> 4) * 8) * 2;          // A-type (Ps)
    __half* Pw = Ps + m0 * AT_S;
    uint32_t pw_b = smem_u32(Pw) + pa_off;

    // Q fragments (4 k-chunks of 16)
    uint32_t qa[4][4];
    #pragma unroll
    for (int kc = 0; kc < 4; kc++) {
        int d0 = kc * 16;
        qa[kc][0] = *(const uint32_t*)&Qb[(size_t)row0 * C3 + d0 + 2 * r    ];
        qa[kc][1] = *(const uint32_t*)&Qb[(size_t)row1 * C3 + d0 + 2 * r    ];
        qa[kc][2] = *(const uint32_t*)&Qb[(size_t)row0 * C3 + d0 + 2 * r + 8];
        qa[kc][3] = *(const uint32_t*)&Qb[(size_t)row1 * C3 + d0 + 2 * r + 8];
    }

    float oa[8][4];
    #pragma unroll
    for (int nt = 0; nt < 8; nt++)
        #pragma unroll
        for (int i = 0; i < 4; i++) oa[nt][i] = 0.f;
    float mi0 = -1e30f, mi1 = -1e30f, li0 = 0.f, li1 = 0.f;

    int ntiles = (q0 >> 6) + 2;
    for (int kt = 0; kt < ntiles; kt++) {
        int k0 = kt << 6;
        __syncthreads();
        // load K,V tiles (64 rows x 64 halves each), natural layout
        #pragma unroll
        for (int it = 0; it < 2; it++) {
            int i = tid + it * 256;
            int rr = i >> 3, sg = (i & 7) * 8;
            *(uint4*)&Ks[rr * AT_S + sg] =
                *(const uint4*)&Kb[(size_t)(k0 + rr) * C3 + sg];
            *(uint4*)&Vs[rr * AT_S + sg] =
                *(const uint4*)&Vb[(size_t)(k0 + rr) * C3 + sg];
        }
        __syncthreads();

        // ---- S = Q K^T ----
        float sc[8][4];
        #pragma unroll
        for (int nt = 0; nt < 8; nt++)
            #pragma unroll
            for (int i = 0; i < 4; i++) sc[nt][i] = 0.f;
        #pragma unroll
        for (int kc = 0; kc < 4; kc++) {
            int kk = kc * 16;
            #pragma unroll
            for (int np = 0; np < 4; np++) {
                uint32_t r0, r1, r2, r3;
                LDSM4(r0, r1, r2, r3,
                      ks_b + kb_off + (uint32_t)((np * 16 * AT_S + kk) * 2));
                uint32_t b0[2] = {r0, r1}, b1[2] = {r2, r3};
                mma16(sc[2 * np],     qa[kc], b0);
                mma16(sc[2 * np + 1], qa[kc], b1);
            }
        }

        // ---- scale + causal mask + row max ----
        float mx0 = -1e30f, mx1 = -1e30f;
        #pragma unroll
        for (int nt = 0; nt < 8; nt++) {
            int c0 = k0 + nt * 8 + 2 * r;
            int c1 = c0 + 1;
            sc[nt][0] = (c0 <= row0) ? sc[nt][0] * 0.03125f : -1e30f;
            sc[nt][1] = (c1 <= row0) ? sc[nt][1] * 0.03125f : -1e30f;
            sc[nt][2] = (c0 <= row1) ? sc[nt][2] * 0.03125f : -1e30f;
            sc[nt][3] = (c1 <= row1) ? sc[nt][3] * 0.03125f : -1e30f;
            mx0 = fmaxf(mx0, fmaxf(sc[nt][0], sc[nt][1]));
            mx1 = fmaxf(mx1, fmaxf(sc[nt][2], sc[nt][3]));
        }
        mx0 = fmaxf(mx0, __shfl_xor_sync(0xffffffffu, mx0, 1));
        mx0 = fmaxf(mx0, __shfl_xor_sync(0xffffffffu, mx0, 2));
        mx1 = fmaxf(mx1, __shfl_xor_sync(0xffffffffu, mx1, 1));
        mx1 = fmaxf(mx1, __shfl_xor_sync(0xffffffffu, mx1, 2));

        float mn0 = fmaxf(mi0, mx0), mn1 = fmaxf(mi1, mx1);
        float corr0 = __expf(mi0 - mn0);
        float corr1 = __expf(mi1 - mn1);

        // ---- exp + P store (raw half2 bits) ----
        float s0 = 0.f, s1 = 0.f;
        #pragma unroll
        for (int nt = 0; nt < 8; nt++) {
            float2 f01, f23;
            uint32_t h01 = exp2h2((sc[nt][0] - mn0) * LOG2E,
                                  (sc[nt][1] - mn0) * LOG2E, &f01);
            uint32_t h23 = exp2h2((sc[nt][2] - mn1) * LOG2E,
                                  (sc[nt][3] - mn1) * LOG2E, &f23);
            s0 += f01.x + f01.y;
            s1 += f23.x + f23.y;
            *(uint32_t*)&Pw[(g    ) * AT_S + nt * 8 + 2 * r] = h01;
            *(uint32_t*)&Pw[(g + 8) * AT_S + nt * 8 + 2 * r] = h23;
        }
        s0 += __shfl_xor_sync(0xffffffffu, s0, 1);
        s0 += __shfl_xor_sync(0xffffffffu, s0, 2);
        s1 += __shfl_xor_sync(0xffffffffu, s1, 1);
        s1 += __shfl_xor_sync(0xffffffffu, s1, 2);
        li0 = li0 * corr0 + s0;
        li1 = li1 * corr1 + s1;
        mi0 = mn0; mi1 = mn1;

        #pragma unroll
        for (int nt = 0; nt < 8; nt++) {
            oa[nt][0] *= corr0; oa[nt][1] *= corr0;
            oa[nt][2] *= corr1; oa[nt][3] *= corr1;
        }
        __syncwarp();

        // ---- O += P V ----
        #pragma unroll
        for (int scx = 0; scx < 4; scx++) {
            int s8 = scx * 16;
            uint32_t pa[4];
            LDSM4(pa[0], pa[1], pa[2], pa[3],
                  pw_b + (uint32_t)(s8 * 2));
            #pragma unroll
            for (int np = 0; np < 4; np++) {
                uint32_t r0, r1, r2, r3;
                LDSM4T(r0, r1, r2, r3,
                       vs_b + vb_off + (uint32_t)((s8 * AT_S + np * 16) * 2));
                uint32_t b0[2] = {r0, r1}, b1[2] = {r2, r3};
                mma16(oa[2 * np],     pa, b0);
                mma16(oa[2 * np + 1], pa, b1);
            }
        }
    }

    float inv0 = 1.f / li0, inv1 = 1.f / li1;
    __half* Ob = O + (size_t)b * T_ * C_ + h * 64;
    #pragma unroll
    for (int nt = 0; nt < 8; nt++) {
        int cc = nt * 8 + 2 * r;
        *(__half2*)&Ob[(size_t)row0 * C_ + cc] =
            __floats2half2_rn(oa[nt][0] * inv0, oa[nt][1] * inv0);
        *(__half2*)&Ob[(size_t)row1 * C_ + cc] =
            __floats2half2_rn(oa[nt][2] * inv1, oa[nt][3] * inv1);
    }
}

// ---------------- launcher -------------------------------------------------
extern "C" void kernel_launch(void* const* d_in, const int* in_sizes, int n_in,
                              void* d_out, int out_size) {
    const float* x     = (const float*)d_in[0];
    const float* Wq    = (const float*)d_in[1];
    const float* Wk    = (const float*)d_in[2];
    const float* Wv    = (const float*)d_in[3];
    const float* Wproj = (const float*)d_in[4];
    const float* bproj = (const float*)d_in[5];
    const float* W1    = (const float*)d_in[6];
    const float* b1    = (const float*)d_in[7];
    const float* W2    = (const float*)d_in[8];
    const float* b2    = (const float*)d_in[9];
    const float* ln1s  = (const float*)d_in[10];
    const float* ln1b  = (const float*)d_in[11];
    const float* ln2s  = (const float*)d_in[12];
    const float* ln2b  = (const float*)d_in[13];
    float* out = (float*)d_out;

    __half *h, *wqkv, *wp, *w1, *w2, *qkv, *attn, *h2, *f1;
    float *x1;
    cudaGetSymbolAddress((void**)&h,    g_h);
    cudaGetSymbolAddress((void**)&wqkv, g_wqkv);
    cudaGetSymbolAddress((void**)&wp,   g_wp);
    cudaGetSymbolAddress((void**)&w1,   g_w1);
    cudaGetSymbolAddress((void**)&w2,   g_w2);
    cudaGetSymbolAddress((void**)&qkv,  g_qkv);
    cudaGetSymbolAddress((void**)&attn, g_attn);
    cudaGetSymbolAddress((void**)&x1,   g_x1);
    cudaGetSymbolAddress((void**)&h2,   g_h2);
    cudaGetSymbolAddress((void**)&f1,   g_f1);

    cudaFuncSetAttribute(attn_h,
                         cudaFuncAttributeMaxDynamicSharedMemorySize, ATT_SMEM_BYTES);
    cudaFuncSetAttribute(hgemm<0, 0>,
                         cudaFuncAttributeMaxDynamicSharedMemorySize, H_SMEM);
    cudaFuncSetAttribute(hgemm<0, 1>,
                         cudaFuncAttributeMaxDynamicSharedMemorySize, H_SMEM);
    cudaFuncSetAttribute(hgemm<1, 1>,
                         cudaFuncAttributeMaxDynamicSharedMemorySize, H_SMEM);

    dim3 tb(32, 8);

    // LN1 (fp16 out) + weight transposes to [N,K] fp16
    ln_kernel<<<BT, 256>>>(x, ln1s, ln1b, h);
    transp_h<<<dim3(2, 32, 16), tb>>>(Wq, wqkv,               C_, 64, (long)C_ * 64, (long)64 * C_);
    transp_h<<<dim3(2, 32, 16), tb>>>(Wk, wqkv + C_ * C_,     C_, 64, (long)C_ * 64, (long)64 * C_);
    transp_h<<<dim3(2, 32, 16), tb>>>(Wv, wqkv + 2 * C_ * C_, C_, 64, (long)C_ * 64, (long)64 * C_);
    transp_h<<<dim3(32, 32, 1),  tb>>>(Wproj, wp, C_, C_, 0, 0);
    transp_h<<<dim3(128, 32, 1), tb>>>(W1, w1, C_, FF, 0, 0);
    transp_h<<<dim3(32, 128, 1), tb>>>(W2, w2, FF, C_, 0, 0);

    // fused QKV projection: fp16 out
    hgemm<0, 1><<<dim3(C3 / 128, BT / 128), 256, H_SMEM>>>(
        h, wqkv, nullptr, nullptr, qkv, BT, C3, C_);

    // attention (fp16 tensor cores)
    attn_h<<<dim3(T_ / 128, B_ * H_), 256, ATT_SMEM_BYTES>>>(qkv, attn);

    // out proj + residual (fp32 out)
    dim3 g1(C_ / 128, BT / 128);
    hgemm<0, 0><<<g1, 256, H_SMEM>>>(attn, wp, bproj, x, x1, BT, C_, C_);

    // LN2 (fp16 out)
    ln_kernel<<<BT, 256>>>(x1, ln2s, ln2b, h2);

    // MLP
    hgemm<1, 1><<<dim3(FF / 128, BT / 128), 256, H_SMEM>>>(
        h2, w1, b1, nullptr, f1, BT, FF, C_);
    hgemm<0, 0><<<g1, 256, H_SMEM>>>(f1, w2, b2, x1, out, BT, C_, FF);
}

// round 9
// speedup vs baseline: 7.1456x; 1.0785x over previous
#include <cuda_runtime.h>
#include <cuda_fp16.h>
#include <cstdint>

// Problem constants
#define B_ 2
#define T_ 2048
#define C_ 1024
#define H_ 16
#define D_ 64
#define BT 4096          // B_*T_
#define FF 4096          // 4*C_
#define C3 3072          // 3*C_

// ---------------- scratch (static device globals) --------------------------
__device__ __half g_h   [BT * C_];   // LN1 output (fp16)
__device__ __half g_wqkv[C3 * C_];   // QKV weights [N=3C, K=C] fp16
__device__ __half g_wp  [C_ * C_];   // Wproj^T [N,K] fp16
__device__ __half g_w1  [FF * C_];   // W1^T [N=FF, K=C] fp16
__device__ __half g_w2  [C_ * FF];   // W2^T [N=C, K=FF] fp16
__device__ __half g_qkv [BT * C3];   // fused q|k|v [B,T,3C] fp16
__device__ __half g_attn[BT * C_];   // concat heads fp16
__device__ float  g_x1  [BT * C_];   // x + attn@Wproj + bproj (fp32)
__device__ __half g_h2  [BT * C_];   // LN2 output fp16
__device__ __half g_f1  [BT * FF];   // relu(h2@W1+b1) fp16

// ---------------- helpers --------------------------------------------------
__device__ __forceinline__ void mma16(float* c, const uint32_t* a, const uint32_t* b) {
    asm volatile(
        "mma.sync.aligned.m16n8k16.row.col.f32.f16.f16.f32 "
        "{%0,%1,%2,%3}, {%4,%5,%6,%7}, {%8,%9}, {%0,%1,%2,%3};"
        : "+f"(c[0]), "+f"(c[1]), "+f"(c[2]), "+f"(c[3])
        : "r"(a[0]), "r"(a[1]), "r"(a[2]), "r"(a[3]), "r"(b[0]), "r"(b[1]));
}
#define LDSM4(R0, R1, R2, R3, addr) \
    asm volatile("ldmatrix.sync.aligned.m8n8.x4.shared.b16 {%0,%1,%2,%3}, [%4];" \
                 : "=r"(R0), "=r"(R1), "=r"(R2), "=r"(R3) : "r"(addr))
#define LDSM4T(R0, R1, R2, R3, addr) \
    asm volatile("ldmatrix.sync.aligned.m8n8.x4.trans.shared.b16 {%0,%1,%2,%3}, [%4];" \
                 : "=r"(R0), "=r"(R1), "=r"(R2), "=r"(R3) : "r"(addr))

__device__ __forceinline__ uint32_t exp2h2(float t0, float t1, float2* f) {
    __half2 hh = __floats2half2_rn(t0, t1);
    uint32_t hin = *reinterpret_cast<uint32_t*>(&hh);
    uint32_t hout;
    asm("ex2.approx.f16x2 %0, %1;" : "=r"(hout) : "r"(hin));
    __half2 he = *reinterpret_cast<__half2*>(&hout);
    *f = __half22float2(he);
    return hout;
}
__device__ __forceinline__ uint32_t smem_u32(const void* p) {
    uint32_t a;
    asm("{ .reg .u64 t; cvta.to.shared.u64 t, %1; cvt.u32.u64 %0, t; }"
        : "=r"(a) : "l"(p));
    return a;
}
#define CP16(dst, src) \
    asm volatile("cp.async.cg.shared.global [%0], [%1], 16;" \
                 :: "r"(dst), "l"(src) : "memory")
#define CP_COMMIT() asm volatile("cp.async.commit_group;" ::: "memory")
#define CP_WAIT2()  asm volatile("cp.async.wait_group 2;"  ::: "memory")

// ---------------- LayerNorm (fp32 in, fp16 out) ---------------------------
__global__ void ln_kernel(const float* __restrict__ x,
                          const float* __restrict__ sc,
                          const float* __restrict__ bi,
                          __half* __restrict__ out) {
    int row = blockIdx.x;
    const float* xr = x + (size_t)row * C_;
    __half* orow = out + (size_t)row * C_;
    int tid = threadIdx.x;

    float4 v = ((const float4*)xr)[tid];
    float s  = v.x + v.y + v.z + v.w;
    float ss = v.x*v.x + v.y*v.y + v.z*v.z + v.w*v.w;
    #pragma unroll
    for (int o = 16; o; o >>= 1) {
        s  += __shfl_xor_sync(0xffffffffu, s,  o);
        ss += __shfl_xor_sync(0xffffffffu, ss, o);
    }
    __shared__ float sm[8], sm2[8];
    if ((tid & 31) == 0) { sm[tid >> 5] = s; sm2[tid >> 5] = ss; }
    __syncthreads();
    if (tid < 32) {
        float a  = (tid < 8) ? sm[tid]  : 0.f;
        float b2 = (tid < 8) ? sm2[tid] : 0.f;
        #pragma unroll
        for (int o = 4; o; o >>= 1) {
            a  += __shfl_xor_sync(0xffffffffu, a,  o);
            b2 += __shfl_xor_sync(0xffffffffu, b2, o);
        }
        if (tid == 0) { sm[0] = a; sm2[0] = b2; }
    }
    __syncthreads();
    float mean = sm[0] * (1.f / C_);
    float var  = sm2[0] * (1.f / C_) - mean * mean;
    float rstd = rsqrtf(var + 1e-6f);

    float4 sv = ((const float4*)sc)[tid];
    float4 bv = ((const float4*)bi)[tid];
    __half2 h0 = __floats2half2_rn((v.x - mean) * rstd * sv.x + bv.x,
                                   (v.y - mean) * rstd * sv.y + bv.y);
    __half2 h1 = __floats2half2_rn((v.z - mean) * rstd * sv.z + bv.z,
                                   (v.w - mean) * rstd * sv.w + bv.w);
    uint2 o8;
    o8.x = *reinterpret_cast<uint32_t*>(&h0);
    o8.y = *reinterpret_cast<uint32_t*>(&h1);
    *(uint2*)&orow[tid * 4] = o8;
}

// ---------------- merged weight prep: all transposes in one launch ---------
// 12288 tile-blocks: [0,3072) QKV heads, [3072,4096) Wproj,
// [4096,8192) W1, [8192,12288) W2.
__global__ void prep_w(const float* __restrict__ Wq, const float* __restrict__ Wk,
                       const float* __restrict__ Wv, const float* __restrict__ Wproj,
                       const float* __restrict__ W1, const float* __restrict__ W2,
                       __half* __restrict__ wqkv, __half* __restrict__ wp,
                       __half* __restrict__ w1, __half* __restrict__ w2) {
    __shared__ float t[32][33];
    int tIdx = blockIdx.x;
    const float* src; __half* dst;
    int R, Cc, bx, by;
    if (tIdx < 3072) {
        int w = tIdx >> 10, rem = tIdx & 1023;
        int head = rem >> 6, q = rem & 63;
        bx = q & 1; by = q >> 1;
        const float* Wsrc = (w == 0) ? Wq : (w == 1) ? Wk : Wv;
        src = Wsrc + (size_t)head * C_ * 64;
        dst = wqkv + (size_t)w * C_ * C_ + (size_t)head * 64 * C_;
        R = C_; Cc = 64;
    } else if (tIdx < 4096) {
        int rem = tIdx - 3072;
        bx = rem & 31; by = rem >> 5;
        src = Wproj; dst = wp; R = C_; Cc = C_;
    } else if (tIdx < 8192) {
        int rem = tIdx - 4096;
        bx = rem & 127; by = rem >> 7;
        src = W1; dst = w1; R = C_; Cc = FF;
    } else {
        int rem = tIdx - 8192;
        bx = rem & 31; by = rem >> 5;
        src = W2; dst = w2; R = FF; Cc = C_;
    }
    int r0 = by * 32, c0 = bx * 32;
    int x = threadIdx.x, y = threadIdx.y;
    #pragma unroll
    for (int i = 0; i < 32; i += 8)
        t[y + i][x] = src[(size_t)(r0 + y + i) * Cc + c0 + x];
    __syncthreads();
    #pragma unroll
    for (int i = 0; i < 32; i += 8)
        dst[(size_t)(c0 + y + i) * R + r0 + x] = __float2half(t[x][y + i]);
}

// ---------------- fp16 GEMM (m16n8k16 + ldmatrix + cp.async 4-stage) -------
#define H_SA 40
#define H_STG_H (128 * H_SA * 2)
#define H_BOFF  (128 * H_SA)
#define H_STG_BY (H_STG_H * 2)        // 20480 bytes
#define H_SMEM  (4 * H_STG_BY)        // 81920 bytes

template <int RELU, int HOUT>
__global__ void __launch_bounds__(256, 2) hgemm(
    const __half* __restrict__ A, const __half* __restrict__ Bw,
    const float* __restrict__ bias, const float* __restrict__ resid,
    void* __restrict__ Cout, int M, int N, int K)
{
    extern __shared__ __half smh[];
    uint32_t sbase = smem_u32(smh);

    int tid  = threadIdx.x;
    int wid  = tid >> 5, lane = tid & 31;
    int g    = lane >> 2, r = lane & 3;
    int bm   = blockIdx.y, bn = blockIdx.x;
    int wm   = (wid & 1) * 64;
    int wn   = (wid >> 1) * 32;

    const __half* Ab = A  + (size_t)bm * 128 * K;
    const __half* Bb = Bw + (size_t)bn * 128 * K;

    int lr = tid >> 2, seg = tid & 3;
    const __half* Asrc = Ab + (size_t)lr * K + seg * 8;
    const __half* Bsrc = Bb + (size_t)lr * K + seg * 8;
    uint32_t ad0 = sbase + (uint32_t)(lr * 80 + seg * 16);
    uint32_t ad1 = ad0 + 64 * 80;
    uint32_t bd0 = sbase + (uint32_t)(H_BOFF * 2 + lr * 80 + seg * 16);
    uint32_t bd1 = bd0 + 64 * 80;
    const size_t a64 = (size_t)64 * K;

    uint32_t aoff = (uint32_t)(((lane & 7) + ((lane >> 3) & 1) * 8) * H_SA
                               + (lane >> 4) * 8) * 2;
    uint32_t boff = (uint32_t)(((lane & 7) + ((lane >> 4) & 1) * 8) * H_SA
                               + ((lane >> 3) & 1) * 8) * 2;

    float c[4][4][4];
    #pragma unroll
    for (int mt = 0; mt < 4; mt++)
        #pragma unroll
        for (int nt = 0; nt < 4; nt++)
            #pragma unroll
            for (int i = 0; i < 4; i++) c[mt][nt][i] = 0.f;

    int nch = K >> 5;

    // prologue: 3 stages in flight
    #pragma unroll
    for (int pc = 0; pc < 3; pc++) {
        uint32_t so = (uint32_t)pc * H_STG_BY;
        int kt = pc << 5;
        CP16(ad0 + so, Asrc + kt);  CP16(ad1 + so, Asrc + a64 + kt);
        CP16(bd0 + so, Bsrc + kt);  CP16(bd1 + so, Bsrc + a64 + kt);
        CP_COMMIT();
    }

    for (int ch = 0; ch < nch; ch++) {
        int st = ch & 3;
        CP_WAIT2();
        __syncthreads();

        uint32_t abase = sbase + (uint32_t)st * H_STG_BY + aoff;
        uint32_t bbase = sbase + (uint32_t)st * H_STG_BY + H_BOFF * 2 + boff;
        #pragma unroll
        for (int ks = 0; ks < 2; ks++) {
            int kk = ks * 16;
            uint32_t af[4][4], bf[4][2];
            #pragma unroll
            for (int mt = 0; mt < 4; mt++)
                LDSM4(af[mt][0], af[mt][1], af[mt][2], af[mt][3],
                      abase + (uint32_t)(((wm + mt * 16) * H_SA + kk) * 2));
            #pragma unroll
            for (int np = 0; np < 2; np++) {
                uint32_t r0, r1, r2, r3;
                LDSM4(r0, r1, r2, r3,
                      bbase + (uint32_t)(((wn + np * 16) * H_SA + kk) * 2));
                bf[2 * np][0] = r0; bf[2 * np][1] = r1;
                bf[2 * np + 1][0] = r2; bf[2 * np + 1][1] = r3;
            }
            #pragma unroll
            for (int mt = 0; mt < 4; mt++)
                #pragma unroll
                for (int nt = 0; nt < 4; nt++)
                    mma16(c[mt][nt], af[mt], bf[nt]);
        }

        int nc3 = ch + 3;
        if (nc3 < nch) {
            int kt = nc3 << 5;
            uint32_t so = (uint32_t)(nc3 & 3) * H_STG_BY;
            CP16(ad0 + so, Asrc + kt);  CP16(ad1 + so, Asrc + a64 + kt);
            CP16(bd0 + so, Bsrc + kt);  CP16(bd1 + so, Bsrc + a64 + kt);
        }
        CP_COMMIT();
    }

    #pragma unroll
    for (int mt = 0; mt < 4; mt++) {
        #pragma unroll
        for (int rr = 0; rr < 2; rr++) {
            int m = bm * 128 + wm + mt * 16 + g + rr * 8;
            const float* Rrow = resid ? resid + (size_t)m * N + bn * 128 : nullptr;
            #pragma unroll
            for (int nt = 0; nt < 4; nt++) {
                int nc = wn + nt * 8 + 2 * r;
                float v0 = c[mt][nt][rr * 2 + 0];
                float v1 = c[mt][nt][rr * 2 + 1];
                if (bias)  { v0 += bias[bn * 128 + nc]; v1 += bias[bn * 128 + nc + 1]; }
                if (resid) { v0 += Rrow[nc]; v1 += Rrow[nc + 1]; }
                if (RELU)  { v0 = fmaxf(v0, 0.f); v1 = fmaxf(v1, 0.f); }
                if (HOUT) {
                    __half* Crow = (__half*)Cout + (size_t)m * N + bn * 128;
                    *(__half2*)&Crow[nc] = __floats2half2_rn(v0, v1);
                } else {
                    float* Crow = (float*)Cout + (size_t)m * N + bn * 128;
                    *(float2*)&Crow[nc] = make_float2(v0, v1);
                }
            }
        }
    }
}

// ---------------- fp16 tensor-core flash attention (occupancy 2) -----------
#define AT_S 72
#define ATT_SMEM_BYTES ((64 * AT_S + 64 * AT_S + 128 * AT_S) * 2)   // 36864
#define LOG2E 1.4426950408889634f

__global__ void __launch_bounds__(256, 2) attn_h(
    const __half* __restrict__ QKV, __half* __restrict__ O)
{
    extern __shared__ __half sma[];
    __half* Ks = sma;
    __half* Vs = Ks + 64 * AT_S;
    __half* Ps = Vs + 64 * AT_S;
    uint32_t ks_b = smem_u32(Ks);
    uint32_t vs_b = smem_u32(Vs);

    int tid = threadIdx.x;
    int wid = tid >> 5, lane = tid & 31;
    int g = lane >> 2, r = lane & 3;
    int b = blockIdx.y >> 4, h = blockIdx.y & 15;
    int q0 = blockIdx.x * 128;
    int m0 = wid * 16;

    const __half* Qb = QKV + (size_t)b * T_ * C3 + h * 64;
    const __half* Kb = Qb + C_;
    const __half* Vb = Qb + 2 * C_;

    int row0 = q0 + m0 + g;
    int row1 = row0 + 8;

    uint32_t kb_off = (uint32_t)(((lane & 7) + ((lane >> 4) & 1) * 8) * AT_S
                                 + ((lane >> 3) & 1) * 8) * 2;
    uint32_t vb_off = (uint32_t)(((lane & 7) + ((lane >> 3) & 1) * 8) * AT_S
                                 + (lane >> 4) * 8) * 2;
    uint32_t pa_off = (uint32_t)(((lane & 7) + ((lane >> 3) & 1) * 8) * AT_S
                                 + (lane >> 4) * 8) * 2;
    __half* Pw = Ps + m0 * AT_S;
    uint32_t pw_b = smem_u32(Pw) + pa_off;

    uint32_t qa[4][4];
    #pragma unroll
    for (int kc = 0; kc < 4; kc++) {
        int d0 = kc * 16;
        qa[kc][0] = *(const uint32_t*)&Qb[(size_t)row0 * C3 + d0 + 2 * r    ];
        qa[kc][1] = *(const uint32_t*)&Qb[(size_t)row1 * C3 + d0 + 2 * r    ];
        qa[kc][2] = *(const uint32_t*)&Qb[(size_t)row0 * C3 + d0 + 2 * r + 8];
        qa[kc][3] = *(const uint32_t*)&Qb[(size_t)row1 * C3 + d0 + 2 * r + 8];
    }

    float oa[8][4];
    #pragma unroll
    for (int nt = 0; nt < 8; nt++)
        #pragma unroll
        for (int i = 0; i < 4; i++) oa[nt][i] = 0.f;
    float mi0 = -1e30f, mi1 = -1e30f, li0 = 0.f, li1 = 0.f;

    int ntiles = (q0 >> 6) + 2;
    for (int kt = 0; kt < ntiles; kt++) {
        int k0 = kt << 6;
        __syncthreads();
        #pragma unroll
        for (int it = 0; it < 2; it++) {
            int i = tid + it * 256;
            int rr = i >> 3, sg = (i & 7) * 8;
            *(uint4*)&Ks[rr * AT_S + sg] =
                *(const uint4*)&Kb[(size_t)(k0 + rr) * C3 + sg];
            *(uint4*)&Vs[rr * AT_S + sg] =
                *(const uint4*)&Vb[(size_t)(k0 + rr) * C3 + sg];
        }
        __syncthreads();

        float sc[8][4];
        #pragma unroll
        for (int nt = 0; nt < 8; nt++)
            #pragma unroll
            for (int i = 0; i < 4; i++) sc[nt][i] = 0.f;
        #pragma unroll
        for (int kc = 0; kc < 4; kc++) {
            int kk = kc * 16;
            #pragma unroll
            for (int np = 0; np < 4; np++) {
                uint32_t r0, r1, r2, r3;
                LDSM4(r0, r1, r2, r3,
                      ks_b + kb_off + (uint32_t)((np * 16 * AT_S + kk) * 2));
                uint32_t b0[2] = {r0, r1}, b1[2] = {r2, r3};
                mma16(sc[2 * np],     qa[kc], b0);
                mma16(sc[2 * np + 1], qa[kc], b1);
            }
        }

        float mx0 = -1e30f, mx1 = -1e30f;
        #pragma unroll
        for (int nt = 0; nt < 8; nt++) {
            int c0 = k0 + nt * 8 + 2 * r;
            int c1 = c0 + 1;
            sc[nt][0] = (c0 <= row0) ? sc[nt][0] * 0.03125f : -1e30f;
            sc[nt][1] = (c1 <= row0) ? sc[nt][1] * 0.03125f : -1e30f;
            sc[nt][2] = (c0 <= row1) ? sc[nt][2] * 0.03125f : -1e30f;
            sc[nt][3] = (c1 <= row1) ? sc[nt][3] * 0.03125f : -1e30f;
            mx0 = fmaxf(mx0, fmaxf(sc[nt][0], sc[nt][1]));
            mx1 = fmaxf(mx1, fmaxf(sc[nt][2], sc[nt][3]));
        }
        mx0 = fmaxf(mx0, __shfl_xor_sync(0xffffffffu, mx0, 1));
        mx0 = fmaxf(mx0, __shfl_xor_sync(0xffffffffu, mx0, 2));
        mx1 = fmaxf(mx1, __shfl_xor_sync(0xffffffffu, mx1, 1));
        mx1 = fmaxf(mx1, __shfl_xor_sync(0xffffffffu, mx1, 2));

        float mn0 = fmaxf(mi0, mx0), mn1 = fmaxf(mi1, mx1);
        float corr0 = __expf(mi0 - mn0);
        float corr1 = __expf(mi1 - mn1);

        float s0 = 0.f, s1 = 0.f;
        #pragma unroll
        for (int nt = 0; nt < 8; nt++) {
            float2 f01, f23;
            uint32_t h01 = exp2h2((sc[nt][0] - mn0) * LOG2E,
                                  (sc[nt][1] - mn0) * LOG2E, &f01);
            uint32_t h23 = exp2h2((sc[nt][2] - mn1) * LOG2E,
                                  (sc[nt][3] - mn1) * LOG2E, &f23);
            s0 += f01.x + f01.y;
            s1 += f23.x + f23.y;
            *(uint32_t*)&Pw[(g    ) * AT_S + nt * 8 + 2 * r] = h01;
            *(uint32_t*)&Pw[(g + 8) * AT_S + nt * 8 + 2 * r] = h23;
        }
        s0 += __shfl_xor_sync(0xffffffffu, s0, 1);
        s0 += __shfl_xor_sync(0xffffffffu, s0, 2);
        s1 += __shfl_xor_sync(0xffffffffu, s1, 1);
        s1 += __shfl_xor_sync(0xffffffffu, s1, 2);
        li0 = li0 * corr0 + s0;
        li1 = li1 * corr1 + s1;
        mi0 = mn0; mi1 = mn1;

        #pragma unroll
        for (int nt = 0; nt < 8; nt++) {
            oa[nt][0] *= corr0; oa[nt][1] *= corr0;
            oa[nt][2] *= corr1; oa[nt][3] *= corr1;
        }
        __syncwarp();

        #pragma unroll
        for (int scx = 0; scx < 4; scx++) {
            int s8 = scx * 16;
            uint32_t pa[4];
            LDSM4(pa[0], pa[1], pa[2], pa[3],
                  pw_b + (uint32_t)(s8 * 2));
            #pragma unroll
            for (int np = 0; np < 4; np++) {
                uint32_t r0, r1, r2, r3;
                LDSM4T(r0, r1, r2, r3,
                       vs_b + vb_off + (uint32_t)((s8 * AT_S + np * 16) * 2));
                uint32_t b0[2] = {r0, r1}, b1[2] = {r2, r3};
                mma16(oa[2 * np],     pa, b0);
                mma16(oa[2 * np + 1], pa, b1);
            }
        }
    }

    float inv0 = 1.f / li0, inv1 = 1.f / li1;
    __half* Ob = O + (size_t)b * T_ * C_ + h * 64;
    #pragma unroll
    for (int nt = 0; nt < 8; nt++) {
        int cc = nt * 8 + 2 * r;
        *(__half2*)&Ob[(size_t)row0 * C_ + cc] =
            __floats2half2_rn(oa[nt][0] * inv0, oa[nt][1] * inv0);
        *(__half2*)&Ob[(size_t)row1 * C_ + cc] =
            __floats2half2_rn(oa[nt][2] * inv1, oa[nt][3] * inv1);
    }
}

// ---------------- launcher -------------------------------------------------
extern "C" void kernel_launch(void* const* d_in, const int* in_sizes, int n_in,
                              void* d_out, int out_size) {
    const float* x     = (const float*)d_in[0];
    const float* Wq    = (const float*)d_in[1];
    const float* Wk    = (const float*)d_in[2];
    const float* Wv    = (const float*)d_in[3];
    const float* Wproj = (const float*)d_in[4];
    const float* bproj = (const float*)d_in[5];
    const float* W1    = (const float*)d_in[6];
    const float* b1    = (const float*)d_in[7];
    const float* W2    = (const float*)d_in[8];
    const float* b2    = (const float*)d_in[9];
    const float* ln1s  = (const float*)d_in[10];
    const float* ln1b  = (const float*)d_in[11];
    const float* ln2s  = (const float*)d_in[12];
    const float* ln2b  = (const float*)d_in[13];
    float* out = (float*)d_out;

    __half *h, *wqkv, *wp, *w1, *w2, *qkv, *attn, *h2, *f1;
    float *x1;
    cudaGetSymbolAddress((void**)&h,    g_h);
    cudaGetSymbolAddress((void**)&wqkv, g_wqkv);
    cudaGetSymbolAddress((void**)&wp,   g_wp);
    cudaGetSymbolAddress((void**)&w1,   g_w1);
    cudaGetSymbolAddress((void**)&w2,   g_w2);
    cudaGetSymbolAddress((void**)&qkv,  g_qkv);
    cudaGetSymbolAddress((void**)&attn, g_attn);
    cudaGetSymbolAddress((void**)&x1,   g_x1);
    cudaGetSymbolAddress((void**)&h2,   g_h2);
    cudaGetSymbolAddress((void**)&f1,   g_f1);

    cudaFuncSetAttribute(attn_h,
                         cudaFuncAttributeMaxDynamicSharedMemorySize, ATT_SMEM_BYTES);
    cudaFuncSetAttribute(hgemm<0, 0>,
                         cudaFuncAttributeMaxDynamicSharedMemorySize, H_SMEM);
    cudaFuncSetAttribute(hgemm<0, 1>,
                         cudaFuncAttributeMaxDynamicSharedMemorySize, H_SMEM);
    cudaFuncSetAttribute(hgemm<1, 1>,
                         cudaFuncAttributeMaxDynamicSharedMemorySize, H_SMEM);

    // LN1 + all weight transposes (one launch)
    ln_kernel<<<BT, 256>>>(x, ln1s, ln1b, h);
    prep_w<<<12288, dim3(32, 8)>>>(Wq, Wk, Wv, Wproj, W1, W2, wqkv, wp, w1, w2);

    // fused QKV projection (fp16 out)
    hgemm<0, 1><<<dim3(C3 / 128, BT / 128), 256, H_SMEM>>>(
        h, wqkv, nullptr, nullptr, qkv, BT, C3, C_);

    // attention (fp16 tensor cores, occupancy 2)
    attn_h<<<dim3(T_ / 128, B_ * H_), 256, ATT_SMEM_BYTES>>>(qkv, attn);

    // out proj + residual (fp32 out)
    dim3 g1(C_ / 128, BT / 128);
    hgemm<0, 0><<<g1, 256, H_SMEM>>>(attn, wp, bproj, x, x1, BT, C_, C_);

    // LN2 (fp16 out)
    ln_kernel<<<BT, 256>>>(x1, ln2s, ln2b, h2);

    // MLP
    hgemm<1, 1><<<dim3(FF / 128, BT / 128), 256, H_SMEM>>>(
        h2, w1, b1, nullptr, f1, BT, FF, C_);
    hgemm<0, 0><<<g1, 256, H_SMEM>>>(f1, w2, b2, x1, out, BT, C_, FF);
}

// round 10
// speedup vs baseline: 7.7296x; 1.0817x over previous
#include <cuda_runtime.h>
#include <cuda_fp16.h>
#include <cstdint>

// Problem constants
#define B_ 2
#define T_ 2048
#define C_ 1024
#define H_ 16
#define D_ 64
#define BT 4096          // B_*T_
#define FF 4096          // 4*C_
#define C3 3072          // 3*C_

// ---------------- scratch (static device globals) --------------------------
__device__ __half g_h   [BT * C_];   // LN1 output (fp16)
__device__ __half g_wqkv[C3 * C_];   // QKV weights [N=3C, K=C] fp16
__device__ __half g_wp  [C_ * C_];   // Wproj^T [N,K] fp16
__device__ __half g_w1  [FF * C_];   // W1^T [N=FF, K=C] fp16
__device__ __half g_w2  [C_ * FF];   // W2^T [N=C, K=FF] fp16
__device__ __half g_qkv [BT * C3];   // fused q|k|v [B,T,3C] fp16
__device__ __half g_attn[BT * C_];   // concat heads fp16
__device__ float  g_x1  [BT * C_];   // x + attn@Wproj + bproj (fp32)
__device__ __half g_h2  [BT * C_];   // LN2 output fp16
__device__ __half g_f1  [BT * FF];   // relu(h2@W1+b1) fp16

// ---------------- helpers --------------------------------------------------
__device__ __forceinline__ void mma16(float* c, const uint32_t* a, const uint32_t* b) {
    asm volatile(
        "mma.sync.aligned.m16n8k16.row.col.f32.f16.f16.f32 "
        "{%0,%1,%2,%3}, {%4,%5,%6,%7}, {%8,%9}, {%0,%1,%2,%3};"
        : "+f"(c[0]), "+f"(c[1]), "+f"(c[2]), "+f"(c[3])
        : "r"(a[0]), "r"(a[1]), "r"(a[2]), "r"(a[3]), "r"(b[0]), "r"(b[1]));
}
#define LDSM4(R0, R1, R2, R3, addr) \
    asm volatile("ldmatrix.sync.aligned.m8n8.x4.shared.b16 {%0,%1,%2,%3}, [%4];" \
                 : "=r"(R0), "=r"(R1), "=r"(R2), "=r"(R3) : "r"(addr))
#define LDSM4T(R0, R1, R2, R3, addr) \
    asm volatile("ldmatrix.sync.aligned.m8n8.x4.trans.shared.b16 {%0,%1,%2,%3}, [%4];" \
                 : "=r"(R0), "=r"(R1), "=r"(R2), "=r"(R3) : "r"(addr))

__device__ __forceinline__ uint32_t exp2h2(float t0, float t1, float2* f) {
    __half2 hh = __floats2half2_rn(t0, t1);
    uint32_t hin = *reinterpret_cast<uint32_t*>(&hh);
    uint32_t hout;
    asm("ex2.approx.f16x2 %0, %1;" : "=r"(hout) : "r"(hin));
    __half2 he = *reinterpret_cast<__half2*>(&hout);
    *f = __half22float2(he);
    return hout;
}
__device__ __forceinline__ uint32_t smem_u32(const void* p) {
    uint32_t a;
    asm("{ .reg .u64 t; cvta.to.shared.u64 t, %1; cvt.u32.u64 %0, t; }"
        : "=r"(a) : "l"(p));
    return a;
}
#define CP16(dst, src) \
    asm volatile("cp.async.cg.shared.global [%0], [%1], 16;" \
                 :: "r"(dst), "l"(src) : "memory")
#define CP_COMMIT() asm volatile("cp.async.commit_group;" ::: "memory")
#define CP_WAIT1()  asm volatile("cp.async.wait_group 1;"  ::: "memory")

// ---------------- LayerNorm (fp32 in, fp16 out) ---------------------------
__global__ void ln_kernel(const float* __restrict__ x,
                          const float* __restrict__ sc,
                          const float* __restrict__ bi,
                          __half* __restrict__ out) {
    int row = blockIdx.x;
    const float* xr = x + (size_t)row * C_;
    __half* orow = out + (size_t)row * C_;
    int tid = threadIdx.x;

    float4 v = ((const float4*)xr)[tid];
    float s  = v.x + v.y + v.z + v.w;
    float ss = v.x*v.x + v.y*v.y + v.z*v.z + v.w*v.w;
    #pragma unroll
    for (int o = 16; o; o >>= 1) {
        s  += __shfl_xor_sync(0xffffffffu, s,  o);
        ss += __shfl_xor_sync(0xffffffffu, ss, o);
    }
    __shared__ float sm[8], sm2[8];
    if ((tid & 31) == 0) { sm[tid >> 5] = s; sm2[tid >> 5] = ss; }
    __syncthreads();
    if (tid < 32) {
        float a  = (tid < 8) ? sm[tid]  : 0.f;
        float b2 = (tid < 8) ? sm2[tid] : 0.f;
        #pragma unroll
        for (int o = 4; o; o >>= 1) {
            a  += __shfl_xor_sync(0xffffffffu, a,  o);
            b2 += __shfl_xor_sync(0xffffffffu, b2, o);
        }
        if (tid == 0) { sm[0] = a; sm2[0] = b2; }
    }
    __syncthreads();
    float mean = sm[0] * (1.f / C_);
    float var  = sm2[0] * (1.f / C_) - mean * mean;
    float rstd = rsqrtf(var + 1e-6f);

    float4 sv = ((const float4*)sc)[tid];
    float4 bv = ((const float4*)bi)[tid];
    __half2 h0 = __floats2half2_rn((v.x - mean) * rstd * sv.x + bv.x,
                                   (v.y - mean) * rstd * sv.y + bv.y);
    __half2 h1 = __floats2half2_rn((v.z - mean) * rstd * sv.z + bv.z,
                                   (v.w - mean) * rstd * sv.w + bv.w);
    uint2 o8;
    o8.x = *reinterpret_cast<uint32_t*>(&h0);
    o8.y = *reinterpret_cast<uint32_t*>(&h1);
    *(uint2*)&orow[tid * 4] = o8;
}

// ---------------- merged weight prep -------------------------------------
__global__ void prep_w(const float* __restrict__ Wq, const float* __restrict__ Wk,
                       const float* __restrict__ Wv, const float* __restrict__ Wproj,
                       const float* __restrict__ W1, const float* __restrict__ W2,
                       __half* __restrict__ wqkv, __half* __restrict__ wp,
                       __half* __restrict__ w1, __half* __restrict__ w2) {
    __shared__ float t[32][33];
    int tIdx = blockIdx.x;
    const float* src; __half* dst;
    int R, Cc, bx, by;
    if (tIdx < 3072) {
        int w = tIdx >> 10, rem = tIdx & 1023;
        int head = rem >> 6, q = rem & 63;
        bx = q & 1; by = q >> 1;
        const float* Wsrc = (w == 0) ? Wq : (w == 1) ? Wk : Wv;
        src = Wsrc + (size_t)head * C_ * 64;
        dst = wqkv + (size_t)w * C_ * C_ + (size_t)head * 64 * C_;
        R = C_; Cc = 64;
    } else if (tIdx < 4096) {
        int rem = tIdx - 3072;
        bx = rem & 31; by = rem >> 5;
        src = Wproj; dst = wp; R = C_; Cc = C_;
    } else if (tIdx < 8192) {
        int rem = tIdx - 4096;
        bx = rem & 127; by = rem >> 7;
        src = W1; dst = w1; R = C_; Cc = FF;
    } else {
        int rem = tIdx - 8192;
        bx = rem & 31; by = rem >> 5;
        src = W2; dst = w2; R = FF; Cc = C_;
    }
    int r0 = by * 32, c0 = bx * 32;
    int x = threadIdx.x, y = threadIdx.y;
    #pragma unroll
    for (int i = 0; i < 32; i += 8)
        t[y + i][x] = src[(size_t)(r0 + y + i) * Cc + c0 + x];
    __syncthreads();
    #pragma unroll
    for (int i = 0; i < 32; i += 8)
        dst[(size_t)(c0 + y + i) * R + r0 + x] = __float2half(t[x][y + i]);
}

// ---------------- fp16 GEMM (BK=64, 3-stage cp.async, ldmatrix) ------------
#define H_SA 72                       // halves stride (144 B)
#define H_STG_H (128 * H_SA * 2)      // A+B halves per stage = 18432
#define H_BOFF  (128 * H_SA)
#define H_STG_BY (H_STG_H * 2)        // 36864 bytes
#define H_SMEM  (3 * H_STG_BY)        // 110592 bytes

template <int RELU, int HOUT>
__global__ void __launch_bounds__(256, 2) hgemm(
    const __half* __restrict__ A, const __half* __restrict__ Bw,
    const float* __restrict__ bias, const float* __restrict__ resid,
    void* __restrict__ Cout, int M, int N, int K)
{
    extern __shared__ __half smh[];
    uint32_t sbase = smem_u32(smh);

    int tid  = threadIdx.x;
    int wid  = tid >> 5, lane = tid & 31;
    int g    = lane >> 2, r = lane & 3;
    int bm   = blockIdx.y, bn = blockIdx.x;
    int wm   = (wid & 1) * 64;
    int wn   = (wid >> 1) * 32;

    const __half* Ab = A  + (size_t)bm * 128 * K;
    const __half* Bb = Bw + (size_t)bn * 128 * K;

    int lr = tid >> 3, seg = tid & 7;           // row 0..31 (+32 per pass)
    const __half* Asrc = Ab + (size_t)lr * K + seg * 8;
    const __half* Bsrc = Bb + (size_t)lr * K + seg * 8;
    uint32_t ad = sbase + (uint32_t)(lr * 144 + seg * 16);
    uint32_t bd = ad + H_BOFF * 2;
    const size_t r32 = (size_t)32 * K;

    uint32_t aoff = (uint32_t)(((lane & 7) + ((lane >> 3) & 1) * 8) * H_SA
                               + (lane >> 4) * 8) * 2;
    uint32_t boff = (uint32_t)(((lane & 7) + ((lane >> 4) & 1) * 8) * H_SA
                               + ((lane >> 3) & 1) * 8) * 2;

    float c[4][4][4];
    #pragma unroll
    for (int mt = 0; mt < 4; mt++)
        #pragma unroll
        for (int nt = 0; nt < 4; nt++)
            #pragma unroll
            for (int i = 0; i < 4; i++) c[mt][nt][i] = 0.f;

    int nch = K >> 6;

    // prologue: 2 stages in flight
    #pragma unroll
    for (int pc = 0; pc < 2; pc++) {
        uint32_t so = (uint32_t)pc * H_STG_BY;
        int kt = pc << 6;
        #pragma unroll
        for (int p = 0; p < 4; p++) {
            CP16(ad + so + (uint32_t)p * 32 * 144, Asrc + p * r32 + kt);
            CP16(bd + so + (uint32_t)p * 32 * 144, Bsrc + p * r32 + kt);
        }
        CP_COMMIT();
    }

    for (int ch = 0; ch < nch; ch++) {
        int st = ch % 3;
        CP_WAIT1();
        __syncthreads();

        uint32_t abase = sbase + (uint32_t)st * H_STG_BY + aoff;
        uint32_t bbase = sbase + (uint32_t)st * H_STG_BY + H_BOFF * 2 + boff;
        #pragma unroll
        for (int ks = 0; ks < 4; ks++) {
            int kk = ks * 16;
            uint32_t af[4][4], bf[4][2];
            #pragma unroll
            for (int mt = 0; mt < 4; mt++)
                LDSM4(af[mt][0], af[mt][1], af[mt][2], af[mt][3],
                      abase + (uint32_t)(((wm + mt * 16) * H_SA + kk) * 2));
            #pragma unroll
            for (int np = 0; np < 2; np++) {
                uint32_t r0, r1, r2, r3;
                LDSM4(r0, r1, r2, r3,
                      bbase + (uint32_t)(((wn + np * 16) * H_SA + kk) * 2));
                bf[2 * np][0] = r0; bf[2 * np][1] = r1;
                bf[2 * np + 1][0] = r2; bf[2 * np + 1][1] = r3;
            }
            #pragma unroll
            for (int mt = 0; mt < 4; mt++)
                #pragma unroll
                for (int nt = 0; nt < 4; nt++)
                    mma16(c[mt][nt], af[mt], bf[nt]);
        }

        int nc2 = ch + 2;
        if (nc2 < nch) {
            int kt = nc2 << 6;
            uint32_t so = (uint32_t)(nc2 % 3) * H_STG_BY;
            #pragma unroll
            for (int p = 0; p < 4; p++) {
                CP16(ad + so + (uint32_t)p * 32 * 144, Asrc + p * r32 + kt);
                CP16(bd + so + (uint32_t)p * 32 * 144, Bsrc + p * r32 + kt);
            }
        }
        CP_COMMIT();
    }

    #pragma unroll
    for (int mt = 0; mt < 4; mt++) {
        #pragma unroll
        for (int rr = 0; rr < 2; rr++) {
            int m = bm * 128 + wm + mt * 16 + g + rr * 8;
            const float* Rrow = resid ? resid + (size_t)m * N + bn * 128 : nullptr;
            #pragma unroll
            for (int nt = 0; nt < 4; nt++) {
                int nc = wn + nt * 8 + 2 * r;
                float v0 = c[mt][nt][rr * 2 + 0];
                float v1 = c[mt][nt][rr * 2 + 1];
                if (bias)  { v0 += bias[bn * 128 + nc]; v1 += bias[bn * 128 + nc + 1]; }
                if (resid) { v0 += Rrow[nc]; v1 += Rrow[nc + 1]; }
                if (RELU)  { v0 = fmaxf(v0, 0.f); v1 = fmaxf(v1, 0.f); }
                if (HOUT) {
                    __half* Crow = (__half*)Cout + (size_t)m * N + bn * 128;
                    *(__half2*)&Crow[nc] = __floats2half2_rn(v0, v1);
                } else {
                    float* Crow = (float*)Cout + (size_t)m * N + bn * 128;
                    *(float2*)&Crow[nc] = make_float2(v0, v1);
                }
            }
        }
    }
}

// ---------------- fp16 flash attention, register-resident P ----------------
// S C-frags repack directly into PV A-frags (identical thread-data mapping).
#define AT_S 72
#define ATT_SMEM_BYTES ((64 * AT_S + 64 * AT_S) * 2)   // 18432 (K + V only)
#define LOG2E 1.4426950408889634f

__global__ void __launch_bounds__(256, 2) attn_h(
    const __half* __restrict__ QKV, __half* __restrict__ O)
{
    extern __shared__ __half sma[];
    __half* Ks = sma;
    __half* Vs = Ks + 64 * AT_S;
    uint32_t ks_b = smem_u32(Ks);
    uint32_t vs_b = smem_u32(Vs);

    int tid = threadIdx.x;
    int wid = tid >> 5, lane = tid & 31;
    int g = lane >> 2, r = lane & 3;
    int b = blockIdx.y >> 4, h = blockIdx.y & 15;
    int q0 = blockIdx.x * 128;
    int m0 = wid * 16;

    const __half* Qb = QKV + (size_t)b * T_ * C3 + h * 64;
    const __half* Kb = Qb + C_;
    const __half* Vb = Qb + 2 * C_;

    int row0 = q0 + m0 + g;
    int row1 = row0 + 8;

    uint32_t kb_off = (uint32_t)(((lane & 7) + ((lane >> 4) & 1) * 8) * AT_S
                                 + ((lane >> 3) & 1) * 8) * 2;
    uint32_t vb_off = (uint32_t)(((lane & 7) + ((lane >> 3) & 1) * 8) * AT_S
                                 + (lane >> 4) * 8) * 2;

    uint32_t qa[4][4];
    #pragma unroll
    for (int kc = 0; kc < 4; kc++) {
        int d0 = kc * 16;
        qa[kc][0] = *(const uint32_t*)&Qb[(size_t)row0 * C3 + d0 + 2 * r    ];
        qa[kc][1] = *(const uint32_t*)&Qb[(size_t)row1 * C3 + d0 + 2 * r    ];
        qa[kc][2] = *(const uint32_t*)&Qb[(size_t)row0 * C3 + d0 + 2 * r + 8];
        qa[kc][3] = *(const uint32_t*)&Qb[(size_t)row1 * C3 + d0 + 2 * r + 8];
    }

    float oa[8][4];
    #pragma unroll
    for (int nt = 0; nt < 8; nt++)
        #pragma unroll
        for (int i = 0; i < 4; i++) oa[nt][i] = 0.f;
    float mi0 = -1e30f, mi1 = -1e30f, li0 = 0.f, li1 = 0.f;

    int ntiles = (q0 >> 6) + 2;
    for (int kt = 0; kt < ntiles; kt++) {
        int k0 = kt << 6;
        __syncthreads();
        #pragma unroll
        for (int it = 0; it < 2; it++) {
            int i = tid + it * 256;
            int rr = i >> 3, sg = (i & 7) * 8;
            *(uint4*)&Ks[rr * AT_S + sg] =
                *(const uint4*)&Kb[(size_t)(k0 + rr) * C3 + sg];
            *(uint4*)&Vs[rr * AT_S + sg] =
                *(const uint4*)&Vb[(size_t)(k0 + rr) * C3 + sg];
        }
        __syncthreads();

        // ---- S = Q K^T ----
        float sc[8][4];
        #pragma unroll
        for (int nt = 0; nt < 8; nt++)
            #pragma unroll
            for (int i = 0; i < 4; i++) sc[nt][i] = 0.f;
        #pragma unroll
        for (int kc = 0; kc < 4; kc++) {
            int kk = kc * 16;
            #pragma unroll
            for (int np = 0; np < 4; np++) {
                uint32_t r0, r1, r2, r3;
                LDSM4(r0, r1, r2, r3,
                      ks_b + kb_off + (uint32_t)((np * 16 * AT_S + kk) * 2));
                uint32_t b0[2] = {r0, r1}, b1[2] = {r2, r3};
                mma16(sc[2 * np],     qa[kc], b0);
                mma16(sc[2 * np + 1], qa[kc], b1);
            }
        }

        // ---- scale + causal mask + row max ----
        float mx0 = -1e30f, mx1 = -1e30f;
        #pragma unroll
        for (int nt = 0; nt < 8; nt++) {
            int c0 = k0 + nt * 8 + 2 * r;
            int c1 = c0 + 1;
            sc[nt][0] = (c0 <= row0) ? sc[nt][0] * 0.03125f : -1e30f;
            sc[nt][1] = (c1 <= row0) ? sc[nt][1] * 0.03125f : -1e30f;
            sc[nt][2] = (c0 <= row1) ? sc[nt][2] * 0.03125f : -1e30f;
            sc[nt][3] = (c1 <= row1) ? sc[nt][3] * 0.03125f : -1e30f;
            mx0 = fmaxf(mx0, fmaxf(sc[nt][0], sc[nt][1]));
            mx1 = fmaxf(mx1, fmaxf(sc[nt][2], sc[nt][3]));
        }
        mx0 = fmaxf(mx0, __shfl_xor_sync(0xffffffffu, mx0, 1));
        mx0 = fmaxf(mx0, __shfl_xor_sync(0xffffffffu, mx0, 2));
        mx1 = fmaxf(mx1, __shfl_xor_sync(0xffffffffu, mx1, 1));
        mx1 = fmaxf(mx1, __shfl_xor_sync(0xffffffffu, mx1, 2));

        float mn0 = fmaxf(mi0, mx0), mn1 = fmaxf(mi1, mx1);
        float corr0 = __expf(mi0 - mn0);
        float corr1 = __expf(mi1 - mn1);

        // ---- exp; keep P packed in registers (hp0 = row g, hp1 = row g+8) ----
        uint32_t hp0[8], hp1[8];
        float s0 = 0.f, s1 = 0.f;
        #pragma unroll
        for (int nt = 0; nt < 8; nt++) {
            float2 f01, f23;
            hp0[nt] = exp2h2((sc[nt][0] - mn0) * LOG2E,
                             (sc[nt][1] - mn0) * LOG2E, &f01);
            hp1[nt] = exp2h2((sc[nt][2] - mn1) * LOG2E,
                             (sc[nt][3] - mn1) * LOG2E, &f23);
            s0 += f01.x + f01.y;
            s1 += f23.x + f23.y;
        }
        s0 += __shfl_xor_sync(0xffffffffu, s0, 1);
        s0 += __shfl_xor_sync(0xffffffffu, s0, 2);
        s1 += __shfl_xor_sync(0xffffffffu, s1, 1);
        s1 += __shfl_xor_sync(0xffffffffu, s1, 2);
        li0 = li0 * corr0 + s0;
        li1 = li1 * corr1 + s1;
        mi0 = mn0; mi1 = mn1;

        #pragma unroll
        for (int nt = 0; nt < 8; nt++) {
            oa[nt][0] *= corr0; oa[nt][1] *= corr0;
            oa[nt][2] *= corr1; oa[nt][3] *= corr1;
        }

        // ---- O += P V (P A-frags direct from C-frag repack) ----
        #pragma unroll
        for (int scx = 0; scx < 4; scx++) {
            int s8 = scx * 16;
            uint32_t pa[4] = {hp0[2 * scx], hp1[2 * scx],
                              hp0[2 * scx + 1], hp1[2 * scx + 1]};
            #pragma unroll
            for (int np = 0; np < 4; np++) {
                uint32_t r0, r1, r2, r3;
                LDSM4T(r0, r1, r2, r3,
                       vs_b + vb_off + (uint32_t)((s8 * AT_S + np * 16) * 2));
                uint32_t b0[2] = {r0, r1}, b1[2] = {r2, r3};
                mma16(oa[2 * np],     pa, b0);
                mma16(oa[2 * np + 1], pa, b1);
            }
        }
    }

    float inv0 = 1.f / li0, inv1 = 1.f / li1;
    __half* Ob = O + (size_t)b * T_ * C_ + h * 64;
    #pragma unroll
    for (int nt = 0; nt < 8; nt++) {
        int cc = nt * 8 + 2 * r;
        *(__half2*)&Ob[(size_t)row0 * C_ + cc] =
            __floats2half2_rn(oa[nt][0] * inv0, oa[nt][1] * inv0);
        *(__half2*)&Ob[(size_t)row1 * C_ + cc] =
            __floats2half2_rn(oa[nt][2] * inv1, oa[nt][3] * inv1);
    }
}

// ---------------- launcher -------------------------------------------------
extern "C" void kernel_launch(void* const* d_in, const int* in_sizes, int n_in,
                              void* d_out, int out_size) {
    const float* x     = (const float*)d_in[0];
    const float* Wq    = (const float*)d_in[1];
    const float* Wk    = (const float*)d_in[2];
    const float* Wv    = (const float*)d_in[3];
    const float* Wproj = (const float*)d_in[4];
    const float* bproj = (const float*)d_in[5];
    const float* W1    = (const float*)d_in[6];
    const float* b1    = (const float*)d_in[7];
    const float* W2    = (const float*)d_in[8];
    const float* b2    = (const float*)d_in[9];
    const float* ln1s  = (const float*)d_in[10];
    const float* ln1b  = (const float*)d_in[11];
    const float* ln2s  = (const float*)d_in[12];
    const float* ln2b  = (const float*)d_in[13];
    float* out = (float*)d_out;

    __half *h, *wqkv, *wp, *w1, *w2, *qkv, *attn, *h2, *f1;
    float *x1;
    cudaGetSymbolAddress((void**)&h,    g_h);
    cudaGetSymbolAddress((void**)&wqkv, g_wqkv);
    cudaGetSymbolAddress((void**)&wp,   g_wp);
    cudaGetSymbolAddress((void**)&w1,   g_w1);
    cudaGetSymbolAddress((void**)&w2,   g_w2);
    cudaGetSymbolAddress((void**)&qkv,  g_qkv);
    cudaGetSymbolAddress((void**)&attn, g_attn);
    cudaGetSymbolAddress((void**)&x1,   g_x1);
    cudaGetSymbolAddress((void**)&h2,   g_h2);
    cudaGetSymbolAddress((void**)&f1,   g_f1);

    cudaFuncSetAttribute(attn_h,
                         cudaFuncAttributeMaxDynamicSharedMemorySize, ATT_SMEM_BYTES);
    cudaFuncSetAttribute(hgemm<0, 0>,
                         cudaFuncAttributeMaxDynamicSharedMemorySize, H_SMEM);
    cudaFuncSetAttribute(hgemm<0, 1>,
                         cudaFuncAttributeMaxDynamicSharedMemorySize, H_SMEM);
    cudaFuncSetAttribute(hgemm<1, 1>,
                         cudaFuncAttributeMaxDynamicSharedMemorySize, H_SMEM);

    // LN1 + merged weight prep
    ln_kernel<<<BT, 256>>>(x, ln1s, ln1b, h);
    prep_w<<<12288, dim3(32, 8)>>>(Wq, Wk, Wv, Wproj, W1, W2, wqkv, wp, w1, w2);

    // fused QKV projection (fp16 out)
    hgemm<0, 1><<<dim3(C3 / 128, BT / 128), 256, H_SMEM>>>(
        h, wqkv, nullptr, nullptr, qkv, BT, C3, C_);

    // attention
    attn_h<<<dim3(T_ / 128, B_ * H_), 256, ATT_SMEM_BYTES>>>(qkv, attn);

    // out proj + residual (fp32 out)
    dim3 g1(C_ / 128, BT / 128);
    hgemm<0, 0><<<g1, 256, H_SMEM>>>(attn, wp, bproj, x, x1, BT, C_, C_);

    // LN2 (fp16 out)
    ln_kernel<<<BT, 256>>>(x1, ln2s, ln2b, h2);

    // MLP
    hgemm<1, 1><<<dim3(FF / 128, BT / 128), 256, H_SMEM>>>(
        h2, w1, b1, nullptr, f1, BT, FF, C_);
    hgemm<0, 0><<<g1, 256, H_SMEM>>>(f1, w2, b2, x1, out, BT, C_, FF);
}